// round 2
// baseline (speedup 1.0000x reference)
#include <cuda_runtime.h>
#include <math.h>

#define TT   2048
#define HID_ 2048
#define NH   16
#define NKV  4
#define HD_  128
#define QKVN ((NH + 2 * NKV) * HD_)   // 3072
#define GRP  (NH / NKV)               // 4

// Scratch (allocation-free rule: static device globals)
__device__ float g_qkv[TT * QKVN];    // ~25 MB
__device__ float g_attn[TT * HID_];   // ~16 MB

// ----------------------------------------------------------------------------
// SGEMM: C[M,N] = A[M,K] @ B[K,N], row-major, M%64==0, N%64==0, K%16==0
// BM=BN=64, BK=16, 256 threads, 4x4 micro-tile per thread
// ----------------------------------------------------------------------------
__global__ __launch_bounds__(256) void sgemm64(
    const float* __restrict__ A, const float* __restrict__ B,
    float* __restrict__ C, int M, int N, int K)
{
    __shared__ float As[16][64];
    __shared__ float Bs[16][64];

    const int tid = threadIdx.x;
    const int tx = tid % 16;
    const int ty = tid / 16;
    const int m0 = blockIdx.y * 64;
    const int n0 = blockIdx.x * 64;

    // A tile loader: thread -> (row = tid/4, 4 consecutive k at (tid%4)*4)
    const int arow  = tid >> 2;
    const int acol4 = (tid & 3) * 4;
    // B tile loader: thread -> (row = tid/16, 4 consecutive n at (tid%16)*4)
    const int brow  = tid >> 4;
    const int bcol4 = (tid & 15) * 4;

    float acc[4][4];
#pragma unroll
    for (int i = 0; i < 4; i++)
#pragma unroll
        for (int j = 0; j < 4; j++) acc[i][j] = 0.f;

    for (int k0 = 0; k0 < K; k0 += 16) {
        float4 av = *(const float4*)&A[(size_t)(m0 + arow) * K + k0 + acol4];
        As[acol4 + 0][arow] = av.x;
        As[acol4 + 1][arow] = av.y;
        As[acol4 + 2][arow] = av.z;
        As[acol4 + 3][arow] = av.w;
        float4 bv = *(const float4*)&B[(size_t)(k0 + brow) * N + n0 + bcol4];
        *(float4*)&Bs[brow][bcol4] = bv;
        __syncthreads();

#pragma unroll
        for (int k = 0; k < 16; k++) {
            float a[4], b[4];
#pragma unroll
            for (int i = 0; i < 4; i++) a[i] = As[k][ty * 4 + i];
#pragma unroll
            for (int j = 0; j < 4; j++) b[j] = Bs[k][tx * 4 + j];
#pragma unroll
            for (int i = 0; i < 4; i++)
#pragma unroll
                for (int j = 0; j < 4; j++) acc[i][j] += a[i] * b[j];
        }
        __syncthreads();
    }

#pragma unroll
    for (int i = 0; i < 4; i++) {
        float4 v = make_float4(acc[i][0], acc[i][1], acc[i][2], acc[i][3]);
        *(float4*)&C[(size_t)(m0 + ty * 4 + i) * N + n0 + tx * 4] = v;
    }
}

// ----------------------------------------------------------------------------
// RoPE in-place on q (heads 0..15) and k (heads 16..19) columns of g_qkv
// ----------------------------------------------------------------------------
__global__ void rope_kernel(float* __restrict__ qkv, const int* __restrict__ pos)
{
    const int t = blockIdx.x;
    const int head = blockIdx.y;          // 0..NH+NKV-1, col offset head*HD_
    const int i = threadIdx.x;            // 0..63 (half of HD)

    float* p = qkv + (size_t)t * QKVN + head * HD_;
    double invf = exp(-log(1000000.0) * (2.0 * (double)i / (double)HD_));
    double fr = (double)pos[t] * invf;
    float c = (float)cos(fr);
    float s = (float)sin(fr);
    float x1 = p[i];
    float x2 = p[i + HD_ / 2];
    p[i]            = x1 * c - x2 * s;
    p[i + HD_ / 2]  = x2 * c + x1 * s;
}

// ----------------------------------------------------------------------------
// Causal GQA attention, online softmax, 32-query tile per block, 128 threads.
// Reads rope'd q/k and v straight out of g_qkv; writes o to g_attn.
// ----------------------------------------------------------------------------
#define BQ 32
#define BS 32

__global__ __launch_bounds__(128) void attn_kernel(
    const float* __restrict__ qkv, const int* __restrict__ pos,
    float* __restrict__ out)
{
    __shared__ float Qs[BQ][HD_ + 1];    // stride 129 -> conflict-free
    __shared__ float KVs[BS][HD_ + 1];   // K tile, reused for V tile
    __shared__ float S[BQ][BS + 1];      // scores -> probabilities
    __shared__ float m_s[BQ], l_s[BQ], alpha_s[BQ];
    __shared__ int   posq[BQ], posk[BS];

    const int h   = blockIdx.y;
    const int q0  = blockIdx.x * BQ;
    const int kvh = h / GRP;
    const int tid = threadIdx.x;
    const float scale = 0.088388347648318447f;  // 1/sqrt(128)

    const int r = tid >> 2;     // query row 0..31
    const int g = tid & 3;      // column group 0..3 (owns cols g*32..g*32+31)
    const int cbase = g * 32;

    // load Q tile
    for (int i = tid; i < BQ * HD_; i += 128) {
        int rr = i >> 7, c = i & 127;
        Qs[rr][c] = qkv[(size_t)(q0 + rr) * QKVN + h * HD_ + c];
    }
    if (tid < BQ) {
        posq[tid] = pos[q0 + tid];
        m_s[tid]  = -1e30f;
        l_s[tid]  = 0.f;
    }

    float o[32];
#pragma unroll
    for (int j = 0; j < 32; j++) o[j] = 0.f;

    const int ktiles = q0 / BS + 1;   // all tiles with any unmasked key
    for (int kt = 0; kt < ktiles; kt++) {
        const int s0 = kt * BS;
        __syncthreads();   // previous iteration done reading KVs (as V)
        // load K tile
        for (int i = tid; i < BS * HD_; i += 128) {
            int rr = i >> 7, c = i & 127;
            KVs[rr][c] = qkv[(size_t)(s0 + rr) * QKVN + HID_ + kvh * HD_ + c];
        }
        if (tid < BS) posk[tid] = pos[s0 + tid];
        __syncthreads();

        // scores: thread (r,g) computes S[r][g + 4j] for j=0..7
        const bool diag = (kt == ktiles - 1);
        float sc[8];
#pragma unroll
        for (int j = 0; j < 8; j++) sc[j] = 0.f;
        for (int d = 0; d < HD_; d++) {
            float qv = Qs[r][d];
#pragma unroll
            for (int j = 0; j < 8; j++) sc[j] += qv * KVs[g + 4 * j][d];
        }
#pragma unroll
        for (int j = 0; j < 8; j++) {
            int s = g + 4 * j;
            float v = sc[j] * scale;
            if (diag && posk[s] > posq[r]) v = -1e30f;
            S[r][s] = v;
        }
        __syncthreads();

        // softmax row update (32 threads) + V load (all threads)
        if (tid < BQ) {
            float mold = m_s[tid];
            float mx = mold;
#pragma unroll
            for (int s = 0; s < BS; s++) mx = fmaxf(mx, S[tid][s]);
            float al = __expf(mold - mx);
            float sum = 0.f;
#pragma unroll
            for (int s = 0; s < BS; s++) {
                float p = __expf(S[tid][s] - mx);
                S[tid][s] = p;
                sum += p;
            }
            m_s[tid] = mx;
            l_s[tid] = l_s[tid] * al + sum;
            alpha_s[tid] = al;
        }
        // load V tile into KVs (K no longer needed)
        for (int i = tid; i < BS * HD_; i += 128) {
            int rr = i >> 7, c = i & 127;
            KVs[rr][c] = qkv[(size_t)(s0 + rr) * QKVN + HID_ + NKV * HD_ + kvh * HD_ + c];
        }
        __syncthreads();

        // O update: o[jj] (col cbase+jj) += P[r][s] * V[s][cbase+jj]
        float al = alpha_s[r];
#pragma unroll
        for (int j = 0; j < 32; j++) o[j] *= al;
#pragma unroll
        for (int ss = 0; ss < BS; ss++) {
            int s = (ss + g * 8) & 31;   // phase-rotate s by group: bank-conflict-free V reads
            float p = S[r][s];
#pragma unroll
            for (int jj = 0; jj < 32; jj++)
                o[jj] += p * KVs[s][cbase + jj];
        }
    }

    __syncthreads();
    float inv_l = 1.f / l_s[r];
#pragma unroll
    for (int jj = 0; jj < 32; jj++)
        out[(size_t)(q0 + r) * HID_ + h * HD_ + cbase + jj] = o[jj] * inv_l;
}

// ----------------------------------------------------------------------------
extern "C" void kernel_launch(void* const* d_in, const int* in_sizes, int n_in,
                              void* d_out, int out_size)
{
    const float* hidden = (const float*)d_in[0];   // [T, HID]
    const float* w_qkv  = (const float*)d_in[1];   // [HID, 3072]
    const float* w_o    = (const float*)d_in[2];   // [HID, HID]
    const int*   posp   = (const int*)d_in[3];     // [T]
    float* out = (float*)d_out;                    // [T, HID]

    float* qkvp;  cudaGetSymbolAddress((void**)&qkvp, g_qkv);
    float* attnp; cudaGetSymbolAddress((void**)&attnp, g_attn);

    // 1) qkv = hidden @ w_qkv    (2048 x 3072 x K=2048)
    sgemm64<<<dim3(QKVN / 64, TT / 64), 256>>>(hidden, w_qkv, qkvp, TT, QKVN, HID_);

    // 2) RoPE in place on q and k head columns
    rope_kernel<<<dim3(TT, NH + NKV), HD_ / 2>>>(qkvp, posp);

    // 3) causal GQA attention -> g_attn
    attn_kernel<<<dim3(TT / BQ, NH), 128>>>(qkvp, posp, attnp);

    // 4) out = attn @ w_o        (2048 x 2048 x 2048)
    sgemm64<<<dim3(HID_ / 64, TT / 64), 256>>>(attnp, w_o, out, TT, HID_, HID_);
}

// round 3
// speedup vs baseline: 1.3989x; 1.3989x over previous
#include <cuda_runtime.h>
#include <math.h>

#define TT   2048
#define HID_ 2048
#define NH   16
#define NKV  4
#define HD_  128
#define QKVN ((NH + 2 * NKV) * HD_)   // 3072
#define GRP  (NH / NKV)               // 4

// Scratch (allocation-free rule: static device globals)
__device__ float g_qkv[TT * QKVN];          // qkv projection output (~25 MB)
__device__ float g_qT[NH * HD_ * TT];       // rope'd Q, d-major: [h*128+d][t]
__device__ float g_kT[NKV * HD_ * TT];      // rope'd K, d-major: [kh*128+d][t]
__device__ float g_attn[TT * HID_];         // attention output (~16 MB)

// ----------------------------------------------------------------------------
// SGEMM: C[M,N] = A[M,K] @ B[K,N], row-major. BM=BN=128, BK=8, 256 threads,
// 8x8 micro-tile, double-buffered smem + register prefetch.
// Requires M%128==0, N%128==0, K%8==0.
// ----------------------------------------------------------------------------
__global__ __launch_bounds__(256) void sgemm128(
    const float* __restrict__ A, const float* __restrict__ B,
    float* __restrict__ C, int M, int N, int K)
{
    __shared__ float As[2][8][132];   // A transposed: As[k][m], pad -> conflict-free stores
    __shared__ float Bs[2][8][128];

    const int tid = threadIdx.x;
    const int m0 = blockIdx.y * 128;
    const int n0 = blockIdx.x * 128;

    // A loader: 128 rows x 8 k, thread -> (arow = tid/2, 4 k at (tid&1)*4)
    const int arow = tid >> 1, ak4 = (tid & 1) * 4;
    // B loader: 8 rows x 128 n, thread -> (brow = tid/32, 4 n at (tid&31)*4)
    const int brow = tid >> 5, bn4 = (tid & 31) * 4;

    const int ty = tid >> 4, tx = tid & 15;   // 16x16 threads of 8x8 outputs

    float acc[8][8];
#pragma unroll
    for (int i = 0; i < 8; i++)
#pragma unroll
        for (int j = 0; j < 8; j++) acc[i][j] = 0.f;

    // preload tile 0
    float4 ra = *(const float4*)&A[(size_t)(m0 + arow) * K + ak4];
    float4 rb = *(const float4*)&B[(size_t)brow * N + n0 + bn4];
    As[0][ak4 + 0][arow] = ra.x;
    As[0][ak4 + 1][arow] = ra.y;
    As[0][ak4 + 2][arow] = ra.z;
    As[0][ak4 + 3][arow] = ra.w;
    *(float4*)&Bs[0][brow][bn4] = rb;
    __syncthreads();

    const int ntiles = K >> 3;
    for (int t = 0; t < ntiles; t++) {
        const int cur = t & 1;
        if (t + 1 < ntiles) {
            ra = *(const float4*)&A[(size_t)(m0 + arow) * K + (t + 1) * 8 + ak4];
            rb = *(const float4*)&B[(size_t)((t + 1) * 8 + brow) * N + n0 + bn4];
        }
#pragma unroll
        for (int k = 0; k < 8; k++) {
            float a[8], b[8];
            *(float4*)&a[0] = *(float4*)&As[cur][k][ty * 8];
            *(float4*)&a[4] = *(float4*)&As[cur][k][ty * 8 + 4];
            *(float4*)&b[0] = *(float4*)&Bs[cur][k][tx * 8];
            *(float4*)&b[4] = *(float4*)&Bs[cur][k][tx * 8 + 4];
#pragma unroll
            for (int i = 0; i < 8; i++)
#pragma unroll
                for (int j = 0; j < 8; j++) acc[i][j] += a[i] * b[j];
        }
        if (t + 1 < ntiles) {
            const int nxt = cur ^ 1;
            As[nxt][ak4 + 0][arow] = ra.x;
            As[nxt][ak4 + 1][arow] = ra.y;
            As[nxt][ak4 + 2][arow] = ra.z;
            As[nxt][ak4 + 3][arow] = ra.w;
            *(float4*)&Bs[nxt][brow][bn4] = rb;
        }
        __syncthreads();
    }

#pragma unroll
    for (int i = 0; i < 8; i++) {
        float* crow = &C[(size_t)(m0 + ty * 8 + i) * N + n0 + tx * 8];
        *(float4*)&crow[0] = make_float4(acc[i][0], acc[i][1], acc[i][2], acc[i][3]);
        *(float4*)&crow[4] = make_float4(acc[i][4], acc[i][5], acc[i][6], acc[i][7]);
    }
}

// ----------------------------------------------------------------------------
// RoPE + transpose: read q/k head columns of g_qkv, write d-major qT/kT.
// block (64, 4): threadIdx.x = half-dim i (0..63), threadIdx.y = t within group
// ----------------------------------------------------------------------------
__global__ void rope_transpose(const float* __restrict__ qkv,
                               const int* __restrict__ pos,
                               float* __restrict__ qT, float* __restrict__ kT)
{
    const int t = blockIdx.x * 4 + threadIdx.y;
    const int head = blockIdx.y;              // 0..19
    const int i = threadIdx.x;                // 0..63

    const float* p = qkv + (size_t)t * QKVN + head * HD_;
    double invf = exp(-log(1000000.0) * (2.0 * (double)i / (double)HD_));
    double fr = (double)pos[t] * invf;
    float c = (float)cos(fr);
    float s = (float)sin(fr);
    float x1 = p[i];
    float x2 = p[i + HD_ / 2];
    float y1 = x1 * c - x2 * s;
    float y2 = x2 * c + x1 * s;

    if (head < NH) {
        qT[(size_t)(head * HD_ + i) * TT + t] = y1;
        qT[(size_t)(head * HD_ + i + 64) * TT + t] = y2;
    } else {
        int kh = head - NH;
        kT[(size_t)(kh * HD_ + i) * TT + t] = y1;
        kT[(size_t)(kh * HD_ + i + 64) * TT + t] = y2;
    }
}

// ----------------------------------------------------------------------------
// Causal GQA flash attention: 64x64 tiles, 256 threads, register-tiled GEMMs.
// Scores computed transposed (St[s][r]) so P@V needs no transpose.
// ----------------------------------------------------------------------------
__global__ __launch_bounds__(256) void attn64(
    const float* __restrict__ qT, const float* __restrict__ kT,
    const float* __restrict__ qkv, const int* __restrict__ pos,
    float* __restrict__ out)
{
    extern __shared__ float sm[];
    float* Qt      = sm;                 // [128][64]  Q tile, d-major
    float* KV      = Qt + 128 * 64;      // [128][64] as Kt  /  [64][128] as Vs
    float* St      = KV + 128 * 64;      // [64][68]  scores -> probabilities
    float* red     = St + 64 * 68;       // [4][64]   reduction partials
    float* m_s     = red + 256;          // [64]
    float* l_s     = m_s + 64;           // [64]
    float* alpha_s = l_s + 64;           // [64]
    int*   posq    = (int*)(alpha_s + 64); // [64]
    int*   posk    = posq + 64;            // [64]

    const int h   = blockIdx.y;
    const int q0  = blockIdx.x * 64;
    const int kvh = h >> 2;               // h / GRP
    const int tid = threadIdx.x;
    const int ty  = tid >> 4, tx = tid & 15;
    const float scale = 0.08838834764831845f;  // 1/sqrt(128)

    // load Q tile (d-major rows of qT, coalesced)
    for (int i = tid; i < 128 * 16; i += 256) {
        int d = i >> 4, c4 = (i & 15) << 2;
        *(float4*)&Qt[d * 64 + c4] =
            *(const float4*)&qT[(size_t)(h * HD_ + d) * TT + q0 + c4];
    }
    if (tid < 64) { posq[tid] = pos[q0 + tid]; m_s[tid] = -1e30f; l_s[tid] = 0.f; }

    float o[4][8];
#pragma unroll
    for (int i = 0; i < 4; i++)
#pragma unroll
        for (int j = 0; j < 8; j++) o[i][j] = 0.f;

    const int ntile = (q0 >> 6) + 1;
    for (int kt = 0; kt < ntile; kt++) {
        const int s0 = kt * 64;
        __syncthreads();   // prev-iter V/St reads done before overwrite

        // load K tile (d-major)
        for (int i = tid; i < 128 * 16; i += 256) {
            int d = i >> 4, c4 = (i & 15) << 2;
            *(float4*)&KV[d * 64 + c4] =
                *(const float4*)&kT[(size_t)(kvh * HD_ + d) * TT + s0 + c4];
        }
        if (tid < 64) posk[tid] = pos[s0 + tid];
        __syncthreads();

        // scores: St[s][r], thread owns s = ty*4.., r = tx*4..
        float accs[4][4];
#pragma unroll
        for (int i = 0; i < 4; i++)
#pragma unroll
            for (int j = 0; j < 4; j++) accs[i][j] = 0.f;
        for (int d = 0; d < 128; d++) {
            float a4[4], b4[4];
            *(float4*)a4 = *(float4*)&KV[d * 64 + ty * 4];
            *(float4*)b4 = *(float4*)&Qt[d * 64 + tx * 4];
#pragma unroll
            for (int i = 0; i < 4; i++)
#pragma unroll
                for (int j = 0; j < 4; j++) accs[i][j] += a4[i] * b4[j];
        }
        const bool diag = (kt == ntile - 1);
#pragma unroll
        for (int i = 0; i < 4; i++) {
            int s = ty * 4 + i;
            float v4[4];
#pragma unroll
            for (int j = 0; j < 4; j++) {
                int r = tx * 4 + j;
                float v = accs[i][j] * scale;
                if (diag && posk[s] > posq[r]) v = -1e30f;
                v4[j] = v;
            }
            *(float4*)&St[s * 68 + tx * 4] = *(float4*)v4;
        }
        __syncthreads();

        // partial max (per 16-s chunk) + V tile load (overwrites Kt, now dead)
        {
            int r = tid & 63, grp = tid >> 6;
            float mx = -1e30f;
#pragma unroll
            for (int s = grp * 16; s < grp * 16 + 16; s++)
                mx = fmaxf(mx, St[s * 68 + r]);
            red[grp * 64 + r] = mx;
        }
        for (int i = tid; i < 64 * 32; i += 256) {
            int s = i >> 5, c4 = (i & 31) << 2;
            *(float4*)&KV[s * 128 + c4] =
                *(const float4*)&qkv[(size_t)(s0 + s) * QKVN + HID_ + NKV * HD_ + kvh * HD_ + c4];
        }
        __syncthreads();

        if (tid < 64) {
            float mold = m_s[tid];
            float mx = fmaxf(fmaxf(red[tid], red[64 + tid]),
                             fmaxf(red[128 + tid], red[192 + tid]));
            mx = fmaxf(mx, mold);
            alpha_s[tid] = __expf(mold - mx);
            m_s[tid] = mx;
        }
        __syncthreads();

        // exponentiate + partial sums
        {
            int r = tid & 63, grp = tid >> 6;
            float mx = m_s[r];
            float sum = 0.f;
#pragma unroll
            for (int s = grp * 16; s < grp * 16 + 16; s++) {
                float pr = __expf(St[s * 68 + r] - mx);
                St[s * 68 + r] = pr;
                sum += pr;
            }
            red[grp * 64 + r] = sum;
        }
        __syncthreads();

        if (tid < 64)
            l_s[tid] = l_s[tid] * alpha_s[tid] +
                       red[tid] + red[64 + tid] + red[128 + tid] + red[192 + tid];

        // O update: thread owns rows r = ty*4.., cols d = tx*8..
#pragma unroll
        for (int i = 0; i < 4; i++) {
            float al = alpha_s[ty * 4 + i];
#pragma unroll
            for (int j = 0; j < 8; j++) o[i][j] *= al;
        }
        for (int s = 0; s < 64; s++) {
            float p4[4], v8[8];
            *(float4*)p4 = *(float4*)&St[s * 68 + ty * 4];
            *(float4*)&v8[0] = *(float4*)&KV[s * 128 + tx * 8];
            *(float4*)&v8[4] = *(float4*)&KV[s * 128 + tx * 8 + 4];
#pragma unroll
            for (int i = 0; i < 4; i++)
#pragma unroll
                for (int j = 0; j < 8; j++) o[i][j] += p4[i] * v8[j];
        }
    }

    __syncthreads();   // last l_s writes visible
#pragma unroll
    for (int i = 0; i < 4; i++) {
        float inv = 1.f / l_s[ty * 4 + i];
        float* orow = &out[(size_t)(q0 + ty * 4 + i) * HID_ + h * HD_ + tx * 8];
        *(float4*)&orow[0] = make_float4(o[i][0] * inv, o[i][1] * inv, o[i][2] * inv, o[i][3] * inv);
        *(float4*)&orow[4] = make_float4(o[i][4] * inv, o[i][5] * inv, o[i][6] * inv, o[i][7] * inv);
    }
}

// ----------------------------------------------------------------------------
extern "C" void kernel_launch(void* const* d_in, const int* in_sizes, int n_in,
                              void* d_out, int out_size)
{
    const float* hidden = (const float*)d_in[0];   // [T, HID]
    const float* w_qkv  = (const float*)d_in[1];   // [HID, 3072]
    const float* w_o    = (const float*)d_in[2];   // [HID, HID]
    const int*   posp   = (const int*)d_in[3];     // [T]
    float* out = (float*)d_out;                    // [T, HID]

    float* qkvp;  cudaGetSymbolAddress((void**)&qkvp, g_qkv);
    float* qTp;   cudaGetSymbolAddress((void**)&qTp, g_qT);
    float* kTp;   cudaGetSymbolAddress((void**)&kTp, g_kT);
    float* attnp; cudaGetSymbolAddress((void**)&attnp, g_attn);

    // attention dynamic smem: Qt+KV+St+red+m/l/alpha floats + pos ints
    const int ATTN_SMEM = (128 * 64 * 2 + 64 * 68 + 256 + 64 * 3) * 4 + 128 * 4;
    cudaFuncSetAttribute((const void*)attn64,
                         cudaFuncAttributeMaxDynamicSharedMemorySize, ATTN_SMEM);

    // 1) qkv = hidden @ w_qkv    (2048 x 3072 x 2048)
    sgemm128<<<dim3(QKVN / 128, TT / 128), 256>>>(hidden, w_qkv, qkvp, TT, QKVN, HID_);

    // 2) RoPE + transpose q,k into d-major buffers
    rope_transpose<<<dim3(TT / 4, NH + NKV), dim3(64, 4)>>>(qkvp, posp, qTp, kTp);

    // 3) causal GQA attention -> g_attn
    attn64<<<dim3(TT / 64, NH), 256, ATTN_SMEM>>>(qTp, kTp, qkvp, posp, attnp);

    // 4) out = attn @ w_o        (2048 x 2048 x 2048)
    sgemm128<<<dim3(HID_ / 128, TT / 128), 256>>>(attnp, w_o, out, TT, HID_, HID_);
}

// round 5
// speedup vs baseline: 2.0654x; 1.4764x over previous
#include <cuda_runtime.h>
#include <cuda_bf16.h>
#include <stdint.h>
#include <math.h>

#define TT   2048
#define HID_ 2048
#define NH   16
#define NKV  4
#define HD_  128
#define QKVN ((NH + 2 * NKV) * HD_)   // 3072
#define GRP  (NH / NKV)               // 4

// ---------------------------------------------------------------------------
// Scratch (allocation-free rule: static device globals)
// ---------------------------------------------------------------------------
__device__ float g_qkv[TT * QKVN];                         // qkv projection (fp32)
__device__ float g_qT[NH * HD_ * TT];                      // rope'd Q, d-major
__device__ float g_kT[NKV * HD_ * TT];                     // rope'd K, d-major
__device__ __align__(256) __nv_bfloat16 g_hh[TT * HID_];   // hidden hi
__device__ __align__(256) __nv_bfloat16 g_hl[TT * HID_];   // hidden lo
__device__ __align__(256) __nv_bfloat16 g_wqh[QKVN * HID_];// w_qkv^T hi [N][K]
__device__ __align__(256) __nv_bfloat16 g_wql[QKVN * HID_];// w_qkv^T lo
__device__ __align__(256) __nv_bfloat16 g_woh[HID_ * HID_];// w_o^T hi
__device__ __align__(256) __nv_bfloat16 g_wol[HID_ * HID_];// w_o^T lo
__device__ __align__(256) __nv_bfloat16 g_ah[TT * HID_];   // attn out hi
__device__ __align__(256) __nv_bfloat16 g_al[TT * HID_];   // attn out lo

// ---------------------------------------------------------------------------
// PTX helpers (baseline ISA only: ldmatrix / mma.sync / cp.async)
// ---------------------------------------------------------------------------
__device__ __forceinline__ uint32_t smem_u32(const void* p) {
    uint32_t a;
    asm("{ .reg .u64 t; cvta.to.shared.u64 t, %1; cvt.u32.u64 %0, t; }" : "=r"(a) : "l"(p));
    return a;
}
#define LDSM4(r, addr) \
    asm volatile("ldmatrix.sync.aligned.m8n8.x4.shared.b16 {%0,%1,%2,%3}, [%4];" \
        : "=r"((r)[0]), "=r"((r)[1]), "=r"((r)[2]), "=r"((r)[3]) : "r"(addr))
#define MMA_BF16(d, a, b0, b1) \
    asm volatile("mma.sync.aligned.m16n8k16.row.col.f32.bf16.bf16.f32 " \
        "{%0,%1,%2,%3},{%4,%5,%6,%7},{%8,%9},{%0,%1,%2,%3};" \
        : "+f"((d)[0]), "+f"((d)[1]), "+f"((d)[2]), "+f"((d)[3]) \
        : "r"((a)[0]), "r"((a)[1]), "r"((a)[2]), "r"((a)[3]), "r"(b0), "r"(b1))
__device__ __forceinline__ void cp16(uint32_t dst, const void* src) {
    asm volatile("cp.async.cg.shared.global [%0], [%1], 16;" :: "r"(dst), "l"(src));
}
#define CP_COMMIT() asm volatile("cp.async.commit_group;" ::: "memory")
#define CP_WAIT0()  asm volatile("cp.async.wait_group 0;" ::: "memory")

// ---------------------------------------------------------------------------
// fp32 -> bf16 hi/lo split (hidden_states)
// ---------------------------------------------------------------------------
__global__ void split_bf16(const float* __restrict__ x,
                           __nv_bfloat16* __restrict__ hi,
                           __nv_bfloat16* __restrict__ lo)
{
    int i = (blockIdx.x * 256 + threadIdx.x) * 4;
    float4 v = *(const float4*)&x[i];
    float vv[4] = {v.x, v.y, v.z, v.w};
    unsigned short hs[4], ls[4];
#pragma unroll
    for (int j = 0; j < 4; j++) {
        __nv_bfloat16 h = __float2bfloat16(vv[j]);
        __nv_bfloat16 l = __float2bfloat16(vv[j] - __bfloat162float(h));
        hs[j] = reinterpret_cast<unsigned short&>(h);
        ls[j] = reinterpret_cast<unsigned short&>(l);
    }
    uint2 hp, lp;
    hp.x = (uint32_t)hs[0] | ((uint32_t)hs[1] << 16);
    hp.y = (uint32_t)hs[2] | ((uint32_t)hs[3] << 16);
    lp.x = (uint32_t)ls[0] | ((uint32_t)ls[1] << 16);
    lp.y = (uint32_t)ls[2] | ((uint32_t)ls[3] << 16);
    *(uint2*)&hi[i] = hp;
    *(uint2*)&lo[i] = lp;
}

// ---------------------------------------------------------------------------
// Weight transpose + split: W[K][N] fp32 -> Wt_hi/Wt_lo [N][K] bf16
// ---------------------------------------------------------------------------
__global__ void transpose_split(const float* __restrict__ W,
                                __nv_bfloat16* __restrict__ Th,
                                __nv_bfloat16* __restrict__ Tl,
                                int K, int N)
{
    __shared__ float sm[32][33];
    const int n0 = blockIdx.x * 32, k0 = blockIdx.y * 32;
    const int tx = threadIdx.x, ty = threadIdx.y;   // 32 x 8
#pragma unroll
    for (int i = 0; i < 4; i++)
        sm[ty + i * 8][tx] = W[(size_t)(k0 + ty + i * 8) * N + n0 + tx];
    __syncthreads();
#pragma unroll
    for (int i = 0; i < 4; i++) {
        float v = sm[tx][ty + i * 8];
        __nv_bfloat16 h = __float2bfloat16(v);
        __nv_bfloat16 l = __float2bfloat16(v - __bfloat162float(h));
        size_t o = (size_t)(n0 + ty + i * 8) * K + k0 + tx;
        Th[o] = h;
        Tl[o] = l;
    }
}

// ---------------------------------------------------------------------------
// mma.sync GEMM: C[M,N] = (Ah+Al)[M,K] @ (Bh+Bl)^T, B stored [N][K] K-major.
// 3-term bf16 (hi*hi + hi*lo + lo*hi). CTA 128x128, BK=64, 2-stage cp.async.
// Warp grid 2x4, warp tile 64x32, mma m16n8k16.
// ---------------------------------------------------------------------------
#define TILE_BYTES  16384               // 128 rows x 128B (64 bf16)
#define STG_AH 0
#define STG_AL 16384
#define STG_BH 32768
#define STG_BL 49152
#define STG_STRIDE 65536
#define GEMM_SMEM (2 * STG_STRIDE + 1024)

__device__ __forceinline__ void issue_tile_loads(
    const __nv_bfloat16* __restrict__ g, uint32_t sdst, int K, int tid)
{
    // 128 rows x 64 bf16 (128B rows), SW128 swizzle; 1024 16B-chunks / 256 thr
#pragma unroll
    for (int i = 0; i < 4; i++) {
        int id = tid + i * 256;
        int row = id >> 3, cc = id & 7;
        uint32_t off = row * 128 + ((cc * 16) ^ ((row & 7) << 4));
        cp16(sdst + off, g + (size_t)row * K + cc * 8);
    }
}

__global__ __launch_bounds__(256, 1) void gemm_mma(
    const __nv_bfloat16* __restrict__ Ah, const __nv_bfloat16* __restrict__ Al,
    const __nv_bfloat16* __restrict__ Bh, const __nv_bfloat16* __restrict__ Bl,
    float* __restrict__ C, int N, int K)
{
    extern __shared__ char smem[];
    const int tid  = threadIdx.x;
    const int wid  = tid >> 5;
    const int lane = tid & 31;
    const int m0 = blockIdx.y * 128;
    const int n0 = blockIdx.x * 128;
    const int m0w = (wid >> 2) * 64;    // warp row offset within tile
    const int n0w = (wid & 3) * 32;     // warp col offset within tile

    const uint32_t dyn = smem_u32(smem);
    const uint32_t tbase = (dyn + 1023) & ~1023u;

    const __nv_bfloat16* gAh = Ah + (size_t)m0 * K;
    const __nv_bfloat16* gAl = Al + (size_t)m0 * K;
    const __nv_bfloat16* gBh = Bh + (size_t)n0 * K;
    const __nv_bfloat16* gBl = Bl + (size_t)n0 * K;

    float acc[4][4][4];
#pragma unroll
    for (int i = 0; i < 4; i++)
#pragma unroll
        for (int j = 0; j < 4; j++)
#pragma unroll
            for (int k = 0; k < 4; k++) acc[i][j][k] = 0.f;

    // per-lane ldmatrix address pieces
    const int lrowA = lane & 15;
    const uint32_t aRow = (uint32_t)(m0w + lrowA) * 128;      // + mt*2048
    const uint32_t xA = (uint32_t)(lrowA & 7) << 4;
    const uint32_t akh = ((uint32_t)lane >> 4) * 16;          // bytes
    const int nrow = n0w + (lane & 7) + ((lane >> 4) & 1) * 8;
    const uint32_t bRow = (uint32_t)nrow * 128;               // + pair*2048
    const uint32_t xB = (uint32_t)(lane & 7) << 4;
    const uint32_t bkh = (((uint32_t)lane >> 3) & 1) * 16;

    // prologue: chunk 0 -> stage 0
    issue_tile_loads(gAh, tbase + STG_AH, K, tid);
    issue_tile_loads(gAl, tbase + STG_AL, K, tid);
    issue_tile_loads(gBh, tbase + STG_BH, K, tid);
    issue_tile_loads(gBl, tbase + STG_BL, K, tid);
    CP_COMMIT();

    const int nchunk = K >> 6;
    for (int c = 0; c < nchunk; c++) {
        CP_WAIT0();
        __syncthreads();
        if (c + 1 < nchunk) {
            const uint32_t st = tbase + ((c + 1) & 1) * STG_STRIDE;
            const int k0 = (c + 1) << 6;
            issue_tile_loads(gAh + k0, st + STG_AH, K, tid);
            issue_tile_loads(gAl + k0, st + STG_AL, K, tid);
            issue_tile_loads(gBh + k0, st + STG_BH, K, tid);
            issue_tile_loads(gBl + k0, st + STG_BL, K, tid);
            CP_COMMIT();
        }
        const uint32_t sc = tbase + (c & 1) * STG_STRIDE;
        const uint32_t sAh = sc + STG_AH, sAl = sc + STG_AL;
        const uint32_t sBh = sc + STG_BH, sBl = sc + STG_BL;

#pragma unroll
        for (int ks = 0; ks < 4; ks++) {
            const uint32_t akt = ((uint32_t)ks * 32 + akh) ^ xA;
            const uint32_t bkt = ((uint32_t)ks * 32 + bkh) ^ xB;
            uint32_t ah[4][4], al[4][4], bh[2][4], bl[2][4];
#pragma unroll
            for (int mt = 0; mt < 4; mt++) {
                uint32_t ao = aRow + mt * 2048 + akt;
                LDSM4(ah[mt], sAh + ao);
                LDSM4(al[mt], sAl + ao);
            }
#pragma unroll
            for (int pr = 0; pr < 2; pr++) {
                uint32_t bo = bRow + pr * 2048 + bkt;
                LDSM4(bh[pr], sBh + bo);
                LDSM4(bl[pr], sBl + bo);
            }
#pragma unroll
            for (int mt = 0; mt < 4; mt++) {
#pragma unroll
                for (int nt = 0; nt < 4; nt++) {
                    const int pr = nt >> 1, hf = (nt & 1) * 2;
                    MMA_BF16(acc[mt][nt], ah[mt], bh[pr][hf], bh[pr][hf + 1]);
                    MMA_BF16(acc[mt][nt], ah[mt], bl[pr][hf], bl[pr][hf + 1]);
                    MMA_BF16(acc[mt][nt], al[mt], bh[pr][hf], bh[pr][hf + 1]);
                }
            }
        }
        __syncthreads();
    }

    // epilogue: d-frag rows (lane>>2, +8), cols (lane&3)*2, +1
    const int rr = lane >> 2, rc = (lane & 3) * 2;
#pragma unroll
    for (int mt = 0; mt < 4; mt++) {
        const int row = m0 + m0w + mt * 16 + rr;
#pragma unroll
        for (int nt = 0; nt < 4; nt++) {
            const int col = n0 + n0w + nt * 8 + rc;
            *(float2*)&C[(size_t)row * N + col] = make_float2(acc[mt][nt][0], acc[mt][nt][1]);
            *(float2*)&C[(size_t)(row + 8) * N + col] = make_float2(acc[mt][nt][2], acc[mt][nt][3]);
        }
    }
}

// ---------------------------------------------------------------------------
// RoPE + transpose q,k into d-major buffers
// ---------------------------------------------------------------------------
__global__ void rope_transpose(const float* __restrict__ qkv,
                               const int* __restrict__ pos,
                               float* __restrict__ qT, float* __restrict__ kT)
{
    const int t = blockIdx.x * 4 + threadIdx.y;
    const int head = blockIdx.y;              // 0..19
    const int i = threadIdx.x;                // 0..63

    const float* p = qkv + (size_t)t * QKVN + head * HD_;
    double invf = exp(-log(1000000.0) * (2.0 * (double)i / (double)HD_));
    double fr = (double)pos[t] * invf;
    float c = (float)cos(fr);
    float s = (float)sin(fr);
    float x1 = p[i];
    float x2 = p[i + HD_ / 2];
    float y1 = x1 * c - x2 * s;
    float y2 = x2 * c + x1 * s;

    if (head < NH) {
        qT[(size_t)(head * HD_ + i) * TT + t] = y1;
        qT[(size_t)(head * HD_ + i + 64) * TT + t] = y2;
    } else {
        int kh = head - NH;
        kT[(size_t)(kh * HD_ + i) * TT + t] = y1;
        kT[(size_t)(kh * HD_ + i + 64) * TT + t] = y2;
    }
}

// ---------------------------------------------------------------------------
// Causal GQA flash attention: 64x64 tiles, 256 threads, register-tiled.
// Heavy q-blocks first. Output written as bf16 hi/lo (feeds GEMM2 directly).
// ---------------------------------------------------------------------------
__global__ __launch_bounds__(256) void attn64(
    const float* __restrict__ qT, const float* __restrict__ kT,
    const float* __restrict__ qkv, const int* __restrict__ pos,
    __nv_bfloat16* __restrict__ oh, __nv_bfloat16* __restrict__ ol)
{
    extern __shared__ float sm[];
    float* Qt      = sm;                 // [128][64]
    float* KV      = Qt + 128 * 64;      // [128][64] Kt / [64][128] Vs
    float* St      = KV + 128 * 64;      // [64][68]
    float* red     = St + 64 * 68;       // [4][64]
    float* m_s     = red + 256;
    float* l_s     = m_s + 64;
    float* alpha_s = l_s + 64;
    int*   posq    = (int*)(alpha_s + 64);
    int*   posk    = posq + 64;

    const int h   = blockIdx.y;
    const int q0  = (gridDim.x - 1 - blockIdx.x) * 64;
    const int kvh = h >> 2;
    const int tid = threadIdx.x;
    const int ty  = tid >> 4, tx = tid & 15;
    const float scale = 0.08838834764831845f;

    for (int i = tid; i < 128 * 16; i += 256) {
        int d = i >> 4, c4 = (i & 15) << 2;
        *(float4*)&Qt[d * 64 + c4] =
            *(const float4*)&qT[(size_t)(h * HD_ + d) * TT + q0 + c4];
    }
    if (tid < 64) { posq[tid] = pos[q0 + tid]; m_s[tid] = -1e30f; l_s[tid] = 0.f; }

    float o[4][8];
#pragma unroll
    for (int i = 0; i < 4; i++)
#pragma unroll
        for (int j = 0; j < 8; j++) o[i][j] = 0.f;

    const int ntile = (q0 >> 6) + 1;
    for (int kt = 0; kt < ntile; kt++) {
        const int s0 = kt * 64;
        __syncthreads();

        for (int i = tid; i < 128 * 16; i += 256) {
            int d = i >> 4, c4 = (i & 15) << 2;
            *(float4*)&KV[d * 64 + c4] =
                *(const float4*)&kT[(size_t)(kvh * HD_ + d) * TT + s0 + c4];
        }
        if (tid < 64) posk[tid] = pos[s0 + tid];
        __syncthreads();

        float accs[4][4];
#pragma unroll
        for (int i = 0; i < 4; i++)
#pragma unroll
            for (int j = 0; j < 4; j++) accs[i][j] = 0.f;
        for (int d = 0; d < 128; d++) {
            float a4[4], b4[4];
            *(float4*)a4 = *(float4*)&KV[d * 64 + ty * 4];
            *(float4*)b4 = *(float4*)&Qt[d * 64 + tx * 4];
#pragma unroll
            for (int i = 0; i < 4; i++)
#pragma unroll
                for (int j = 0; j < 4; j++) accs[i][j] += a4[i] * b4[j];
        }
        const bool diag = (kt == ntile - 1);
#pragma unroll
        for (int i = 0; i < 4; i++) {
            int s = ty * 4 + i;
            float v4[4];
#pragma unroll
            for (int j = 0; j < 4; j++) {
                int r = tx * 4 + j;
                float v = accs[i][j] * scale;
                if (diag && posk[s] > posq[r]) v = -1e30f;
                v4[j] = v;
            }
            *(float4*)&St[s * 68 + tx * 4] = *(float4*)v4;
        }
        __syncthreads();

        {
            int r = tid & 63, grp = tid >> 6;
            float mx = -1e30f;
#pragma unroll
            for (int s = grp * 16; s < grp * 16 + 16; s++)
                mx = fmaxf(mx, St[s * 68 + r]);
            red[grp * 64 + r] = mx;
        }
        for (int i = tid; i < 64 * 32; i += 256) {
            int s = i >> 5, c4 = (i & 31) << 2;
            *(float4*)&KV[s * 128 + c4] =
                *(const float4*)&qkv[(size_t)(s0 + s) * QKVN + HID_ + NKV * HD_ + kvh * HD_ + c4];
        }
        __syncthreads();

        if (tid < 64) {
            float mold = m_s[tid];
            float mx = fmaxf(fmaxf(red[tid], red[64 + tid]),
                             fmaxf(red[128 + tid], red[192 + tid]));
            mx = fmaxf(mx, mold);
            alpha_s[tid] = __expf(mold - mx);
            m_s[tid] = mx;
        }
        __syncthreads();

        {
            int r = tid & 63, grp = tid >> 6;
            float mx = m_s[r];
            float sum = 0.f;
#pragma unroll
            for (int s = grp * 16; s < grp * 16 + 16; s++) {
                float pr = __expf(St[s * 68 + r] - mx);
                St[s * 68 + r] = pr;
                sum += pr;
            }
            red[grp * 64 + r] = sum;
        }
        __syncthreads();

        if (tid < 64)
            l_s[tid] = l_s[tid] * alpha_s[tid] +
                       red[tid] + red[64 + tid] + red[128 + tid] + red[192 + tid];

#pragma unroll
        for (int i = 0; i < 4; i++) {
            float al = alpha_s[ty * 4 + i];
#pragma unroll
            for (int j = 0; j < 8; j++) o[i][j] *= al;
        }
        for (int s = 0; s < 64; s++) {
            float p4[4], v8[8];
            *(float4*)p4 = *(float4*)&St[s * 68 + ty * 4];
            *(float4*)&v8[0] = *(float4*)&KV[s * 128 + tx * 8];
            *(float4*)&v8[4] = *(float4*)&KV[s * 128 + tx * 8 + 4];
#pragma unroll
            for (int i = 0; i < 4; i++)
#pragma unroll
                for (int j = 0; j < 8; j++) o[i][j] += p4[i] * v8[j];
        }
    }

    __syncthreads();
#pragma unroll
    for (int i = 0; i < 4; i++) {
        float inv = 1.f / l_s[ty * 4 + i];
        unsigned short hs[8], ls[8];
#pragma unroll
        for (int j = 0; j < 8; j++) {
            float val = o[i][j] * inv;
            __nv_bfloat16 hb = __float2bfloat16(val);
            __nv_bfloat16 lb = __float2bfloat16(val - __bfloat162float(hb));
            hs[j] = reinterpret_cast<unsigned short&>(hb);
            ls[j] = reinterpret_cast<unsigned short&>(lb);
        }
        size_t idx = (size_t)(q0 + ty * 4 + i) * HID_ + h * HD_ + tx * 8;
        uint4 hv, lv;
        hv.x = (uint32_t)hs[0] | ((uint32_t)hs[1] << 16);
        hv.y = (uint32_t)hs[2] | ((uint32_t)hs[3] << 16);
        hv.z = (uint32_t)hs[4] | ((uint32_t)hs[5] << 16);
        hv.w = (uint32_t)hs[6] | ((uint32_t)hs[7] << 16);
        lv.x = (uint32_t)ls[0] | ((uint32_t)ls[1] << 16);
        lv.y = (uint32_t)ls[2] | ((uint32_t)ls[3] << 16);
        lv.z = (uint32_t)ls[4] | ((uint32_t)ls[5] << 16);
        lv.w = (uint32_t)ls[6] | ((uint32_t)ls[7] << 16);
        *(uint4*)&oh[idx] = hv;
        *(uint4*)&ol[idx] = lv;
    }
}

// ---------------------------------------------------------------------------
extern "C" void kernel_launch(void* const* d_in, const int* in_sizes, int n_in,
                              void* d_out, int out_size)
{
    const float* hidden = (const float*)d_in[0];   // [T, HID]
    const float* w_qkv  = (const float*)d_in[1];   // [HID, 3072]
    const float* w_o    = (const float*)d_in[2];   // [HID, HID]
    const int*   posp   = (const int*)d_in[3];     // [T]
    float* out = (float*)d_out;                    // [T, HID]

    float* qkvp;  cudaGetSymbolAddress((void**)&qkvp, g_qkv);
    float* qTp;   cudaGetSymbolAddress((void**)&qTp, g_qT);
    float* kTp;   cudaGetSymbolAddress((void**)&kTp, g_kT);
    __nv_bfloat16 *hh, *hl, *wqh, *wql, *woh, *wol, *ah, *al;
    cudaGetSymbolAddress((void**)&hh, g_hh);
    cudaGetSymbolAddress((void**)&hl, g_hl);
    cudaGetSymbolAddress((void**)&wqh, g_wqh);
    cudaGetSymbolAddress((void**)&wql, g_wql);
    cudaGetSymbolAddress((void**)&woh, g_woh);
    cudaGetSymbolAddress((void**)&wol, g_wol);
    cudaGetSymbolAddress((void**)&ah, g_ah);
    cudaGetSymbolAddress((void**)&al, g_al);

    cudaFuncSetAttribute((const void*)gemm_mma,
                         cudaFuncAttributeMaxDynamicSharedMemorySize, GEMM_SMEM);
    const int ATTN_SMEM = (128 * 64 * 2 + 64 * 68 + 256 + 64 * 3) * 4 + 128 * 4;
    cudaFuncSetAttribute((const void*)attn64,
                         cudaFuncAttributeMaxDynamicSharedMemorySize, ATTN_SMEM);

    // 0) convert operands to bf16 hi/lo
    split_bf16<<<TT * HID_ / 1024, 256>>>(hidden, hh, hl);
    transpose_split<<<dim3(QKVN / 32, HID_ / 32), dim3(32, 8)>>>(w_qkv, wqh, wql, HID_, QKVN);
    transpose_split<<<dim3(HID_ / 32, HID_ / 32), dim3(32, 8)>>>(w_o, woh, wol, HID_, HID_);

    // 1) qkv = hidden @ w_qkv (mma.sync, 3x-bf16)
    gemm_mma<<<dim3(QKVN / 128, TT / 128), 256, GEMM_SMEM>>>(hh, hl, wqh, wql, qkvp, QKVN, HID_);

    // 2) RoPE + transpose
    rope_transpose<<<dim3(TT / 4, NH + NKV), dim3(64, 4)>>>(qkvp, posp, qTp, kTp);

    // 3) attention (writes bf16 hi/lo)
    attn64<<<dim3(TT / 64, NH), 256, ATTN_SMEM>>>(qTp, kTp, qkvp, posp, ah, al);

    // 4) out = attn @ w_o (mma.sync, 3x-bf16)
    gemm_mma<<<dim3(HID_ / 128, TT / 128), 256, GEMM_SMEM>>>(ah, al, woh, wol, out, HID_, HID_);
}

// round 12
// speedup vs baseline: 3.5538x; 1.7206x over previous
#include <cuda_runtime.h>
#include <cuda_bf16.h>
#include <stdint.h>
#include <math.h>

#define TT   2048
#define HID_ 2048
#define NH   16
#define NKV  4
#define HD_  128
#define QKVN ((NH + 2 * NKV) * HD_)   // 3072
#define GRP  (NH / NKV)               // 4

// ---------------------------------------------------------------------------
// Scratch (allocation-free rule: static device globals)
// ---------------------------------------------------------------------------
__device__ float g_qkv[TT * QKVN];                          // qkv projection (fp32)
__device__ __align__(256) __nv_bfloat16 g_hh[TT * HID_];    // hidden hi
__device__ __align__(256) __nv_bfloat16 g_hl[TT * HID_];    // hidden lo
__device__ __align__(256) __nv_bfloat16 g_wqh[QKVN * HID_]; // w_qkv^T hi [N][K]
__device__ __align__(256) __nv_bfloat16 g_wql[QKVN * HID_]; // w_qkv^T lo
__device__ __align__(256) __nv_bfloat16 g_woh[HID_ * HID_]; // w_o^T hi
__device__ __align__(256) __nv_bfloat16 g_wol[HID_ * HID_]; // w_o^T lo
__device__ __align__(256) __nv_bfloat16 g_ah[TT * HID_];    // attn out hi
__device__ __align__(256) __nv_bfloat16 g_al[TT * HID_];    // attn out lo
__device__ __align__(256) __nv_bfloat16 g_qb[NH * TT * HD_];  // rope'd Q bf16 [h][t][d]
__device__ __align__(256) __nv_bfloat16 g_kb[NKV * TT * HD_]; // rope'd K bf16 [kh][t][d]
__device__ __align__(256) __nv_bfloat16 g_vh[NKV * TT * HD_]; // V hi bf16 [kh][t][d]
__device__ __align__(256) __nv_bfloat16 g_vl[NKV * TT * HD_]; // V lo bf16 [kh][t][d]

// ---------------------------------------------------------------------------
// PTX helpers (baseline ISA only: ldmatrix / mma.sync / cp.async)
// ---------------------------------------------------------------------------
__device__ __forceinline__ uint32_t smem_u32(const void* p) {
    uint32_t a;
    asm("{ .reg .u64 t; cvta.to.shared.u64 t, %1; cvt.u32.u64 %0, t; }" : "=r"(a) : "l"(p));
    return a;
}
#define LDSM4(r, addr) \
    asm volatile("ldmatrix.sync.aligned.m8n8.x4.shared.b16 {%0,%1,%2,%3}, [%4];" \
        : "=r"((r)[0]), "=r"((r)[1]), "=r"((r)[2]), "=r"((r)[3]) : "r"(addr))
#define LDSM4T(r, addr) \
    asm volatile("ldmatrix.sync.aligned.m8n8.x4.trans.shared.b16 {%0,%1,%2,%3}, [%4];" \
        : "=r"((r)[0]), "=r"((r)[1]), "=r"((r)[2]), "=r"((r)[3]) : "r"(addr))
#define MMA_BF16(d, a, b0, b1) \
    asm volatile("mma.sync.aligned.m16n8k16.row.col.f32.bf16.bf16.f32 " \
        "{%0,%1,%2,%3},{%4,%5,%6,%7},{%8,%9},{%0,%1,%2,%3};" \
        : "+f"((d)[0]), "+f"((d)[1]), "+f"((d)[2]), "+f"((d)[3]) \
        : "r"((a)[0]), "r"((a)[1]), "r"((a)[2]), "r"((a)[3]), "r"(b0), "r"(b1))
__device__ __forceinline__ void cp16(uint32_t dst, const void* src) {
    asm volatile("cp.async.cg.shared.global [%0], [%1], 16;" :: "r"(dst), "l"(src));
}
#define CP_COMMIT() asm volatile("cp.async.commit_group;" ::: "memory")
#define CP_WAIT0()  asm volatile("cp.async.wait_group 0;" ::: "memory")
__device__ __forceinline__ float ex2(float x) {
    float r;
    asm("ex2.approx.ftz.f32 %0, %1;" : "=f"(r) : "f"(x));
    return r;
}
__device__ __forceinline__ uint32_t packbf(float a, float b) {
    __nv_bfloat162 t = __floats2bfloat162_rn(a, b);
    return reinterpret_cast<uint32_t&>(t);
}
// pack hi(bf16) of (a,b) and lo residual pair
__device__ __forceinline__ void split_pack(float a, float b, uint32_t& h, uint32_t& l) {
    __nv_bfloat16 ha = __float2bfloat16(a), hb = __float2bfloat16(b);
    h = (uint32_t)reinterpret_cast<unsigned short&>(ha) |
        ((uint32_t)reinterpret_cast<unsigned short&>(hb) << 16);
    l = packbf(a - __bfloat162float(ha), b - __bfloat162float(hb));
}

// ---------------------------------------------------------------------------
// fp32 -> bf16 hi/lo split (hidden_states)
// ---------------------------------------------------------------------------
__global__ void split_bf16(const float* __restrict__ x,
                           __nv_bfloat16* __restrict__ hi,
                           __nv_bfloat16* __restrict__ lo)
{
    int i = (blockIdx.x * 256 + threadIdx.x) * 4;
    float4 v = *(const float4*)&x[i];
    uint2 hp, lp;
    split_pack(v.x, v.y, hp.x, lp.x);
    split_pack(v.z, v.w, hp.y, lp.y);
    *(uint2*)&hi[i] = hp;
    *(uint2*)&lo[i] = lp;
}

// ---------------------------------------------------------------------------
// Weight transpose + split: W[K][N] fp32 -> Wt_hi/Wt_lo [N][K] bf16
// ---------------------------------------------------------------------------
__global__ void transpose_split(const float* __restrict__ W,
                                __nv_bfloat16* __restrict__ Th,
                                __nv_bfloat16* __restrict__ Tl,
                                int K, int N)
{
    __shared__ float sm[32][33];
    const int n0 = blockIdx.x * 32, k0 = blockIdx.y * 32;
    const int tx = threadIdx.x, ty = threadIdx.y;   // 32 x 8
#pragma unroll
    for (int i = 0; i < 4; i++)
        sm[ty + i * 8][tx] = W[(size_t)(k0 + ty + i * 8) * N + n0 + tx];
    __syncthreads();
#pragma unroll
    for (int i = 0; i < 4; i++) {
        float v = sm[tx][ty + i * 8];
        __nv_bfloat16 h = __float2bfloat16(v);
        __nv_bfloat16 l = __float2bfloat16(v - __bfloat162float(h));
        size_t o = (size_t)(n0 + ty + i * 8) * K + k0 + tx;
        Th[o] = h;
        Tl[o] = l;
    }
}

// ---------------------------------------------------------------------------
// mma.sync GEMM: C[M,N] = (Ah+Al)[M,K] @ (Bh+Bl)^T, B stored [N][K] K-major.
// 3-term bf16. CTA 128x128, BK=64, 2-stage cp.async. Warp 64x32, m16n8k16.
// ---------------------------------------------------------------------------
#define STG_AH 0
#define STG_AL 16384
#define STG_BH 32768
#define STG_BL 49152
#define STG_STRIDE 65536
#define GEMM_SMEM (2 * STG_STRIDE + 1024)

__device__ __forceinline__ void issue_tile_loads(
    const __nv_bfloat16* __restrict__ g, uint32_t sdst, int K, int tid)
{
#pragma unroll
    for (int i = 0; i < 4; i++) {
        int id = tid + i * 256;
        int row = id >> 3, cc = id & 7;
        uint32_t off = row * 128 + ((cc * 16) ^ ((row & 7) << 4));
        cp16(sdst + off, g + (size_t)row * K + cc * 8);
    }
}

__global__ __launch_bounds__(256, 1) void gemm_mma(
    const __nv_bfloat16* __restrict__ Ah, const __nv_bfloat16* __restrict__ Al,
    const __nv_bfloat16* __restrict__ Bh, const __nv_bfloat16* __restrict__ Bl,
    float* __restrict__ C, int N, int K)
{
    extern __shared__ char smem[];
    const int tid  = threadIdx.x;
    const int wid  = tid >> 5;
    const int lane = tid & 31;
    const int m0 = blockIdx.y * 128;
    const int n0 = blockIdx.x * 128;
    const int m0w = (wid >> 2) * 64;
    const int n0w = (wid & 3) * 32;

    const uint32_t dyn = smem_u32(smem);
    const uint32_t tbase = (dyn + 1023) & ~1023u;

    const __nv_bfloat16* gAh = Ah + (size_t)m0 * K;
    const __nv_bfloat16* gAl = Al + (size_t)m0 * K;
    const __nv_bfloat16* gBh = Bh + (size_t)n0 * K;
    const __nv_bfloat16* gBl = Bl + (size_t)n0 * K;

    float acc[4][4][4];
#pragma unroll
    for (int i = 0; i < 4; i++)
#pragma unroll
        for (int j = 0; j < 4; j++)
#pragma unroll
            for (int k = 0; k < 4; k++) acc[i][j][k] = 0.f;

    const int lrowA = lane & 15;
    const uint32_t aRow = (uint32_t)(m0w + lrowA) * 128;
    const uint32_t xA = (uint32_t)(lrowA & 7) << 4;
    const uint32_t akh = ((uint32_t)lane >> 4) * 16;
    const int nrow = n0w + (lane & 7) + ((lane >> 4) & 1) * 8;
    const uint32_t bRow = (uint32_t)nrow * 128;
    const uint32_t xB = (uint32_t)(lane & 7) << 4;
    const uint32_t bkh = (((uint32_t)lane >> 3) & 1) * 16;

    issue_tile_loads(gAh, tbase + STG_AH, K, tid);
    issue_tile_loads(gAl, tbase + STG_AL, K, tid);
    issue_tile_loads(gBh, tbase + STG_BH, K, tid);
    issue_tile_loads(gBl, tbase + STG_BL, K, tid);
    CP_COMMIT();

    const int nchunk = K >> 6;
    for (int c = 0; c < nchunk; c++) {
        CP_WAIT0();
        __syncthreads();
        if (c + 1 < nchunk) {
            const uint32_t st = tbase + ((c + 1) & 1) * STG_STRIDE;
            const int k0 = (c + 1) << 6;
            issue_tile_loads(gAh + k0, st + STG_AH, K, tid);
            issue_tile_loads(gAl + k0, st + STG_AL, K, tid);
            issue_tile_loads(gBh + k0, st + STG_BH, K, tid);
            issue_tile_loads(gBl + k0, st + STG_BL, K, tid);
            CP_COMMIT();
        }
        const uint32_t sc = tbase + (c & 1) * STG_STRIDE;
        const uint32_t sAh = sc + STG_AH, sAl = sc + STG_AL;
        const uint32_t sBh = sc + STG_BH, sBl = sc + STG_BL;

#pragma unroll
        for (int ks = 0; ks < 4; ks++) {
            const uint32_t akt = ((uint32_t)ks * 32 + akh) ^ xA;
            const uint32_t bkt = ((uint32_t)ks * 32 + bkh) ^ xB;
            uint32_t ah[4][4], al[4][4], bh[2][4], bl[2][4];
#pragma unroll
            for (int mt = 0; mt < 4; mt++) {
                uint32_t ao = aRow + mt * 2048 + akt;
                LDSM4(ah[mt], sAh + ao);
                LDSM4(al[mt], sAl + ao);
            }
#pragma unroll
            for (int pr = 0; pr < 2; pr++) {
                uint32_t bo = bRow + pr * 2048 + bkt;
                LDSM4(bh[pr], sBh + bo);
                LDSM4(bl[pr], sBl + bo);
            }
#pragma unroll
            for (int mt = 0; mt < 4; mt++) {
#pragma unroll
                for (int nt = 0; nt < 4; nt++) {
                    const int pr = nt >> 1, hf = (nt & 1) * 2;
                    MMA_BF16(acc[mt][nt], ah[mt], bh[pr][hf], bh[pr][hf + 1]);
                    MMA_BF16(acc[mt][nt], ah[mt], bl[pr][hf], bl[pr][hf + 1]);
                    MMA_BF16(acc[mt][nt], al[mt], bh[pr][hf], bh[pr][hf + 1]);
                }
            }
        }
        __syncthreads();
    }

    const int rr = lane >> 2, rc = (lane & 3) * 2;
#pragma unroll
    for (int mt = 0; mt < 4; mt++) {
        const int row = m0 + m0w + mt * 16 + rr;
#pragma unroll
        for (int nt = 0; nt < 4; nt++) {
            const int col = n0 + n0w + nt * 8 + rc;
            *(float2*)&C[(size_t)row * N + col] = make_float2(acc[mt][nt][0], acc[mt][nt][1]);
            *(float2*)&C[(size_t)(row + 8) * N + col] = make_float2(acc[mt][nt][2], acc[mt][nt][3]);
        }
    }
}

// ---------------------------------------------------------------------------
// RoPE + convert: q/k rope'd -> bf16; v -> bf16 hi/lo; head-major layouts
// grid (T/4, NH+2*NKV), block (64,4)
// ---------------------------------------------------------------------------
__global__ void rope_convert(const float* __restrict__ qkv,
                             const int* __restrict__ pos,
                             __nv_bfloat16* __restrict__ qb,
                             __nv_bfloat16* __restrict__ kb,
                             __nv_bfloat16* __restrict__ vh,
                             __nv_bfloat16* __restrict__ vl)
{
    const int t = blockIdx.x * 4 + threadIdx.y;
    const int head = blockIdx.y;              // 0..27
    const int i = threadIdx.x;                // 0..63

    if (head < NH + NKV) {
        const float* p = qkv + (size_t)t * QKVN + head * HD_;
        double invf = exp(-log(1000000.0) * (2.0 * (double)i / (double)HD_));
        double fr = (double)pos[t] * invf;
        float c = (float)cos(fr);
        float s = (float)sin(fr);
        float x1 = p[i];
        float x2 = p[i + HD_ / 2];
        float y1 = x1 * c - x2 * s;
        float y2 = x2 * c + x1 * s;
        if (head < NH) {
            __nv_bfloat16* q = qb + ((size_t)head * TT + t) * HD_;
            q[i] = __float2bfloat16(y1);
            q[i + 64] = __float2bfloat16(y2);
        } else {
            __nv_bfloat16* k = kb + ((size_t)(head - NH) * TT + t) * HD_;
            k[i] = __float2bfloat16(y1);
            k[i + 64] = __float2bfloat16(y2);
        }
    } else {
        const int kh = head - NH - NKV;
        const float* p = qkv + (size_t)t * QKVN + HID_ + NKV * HD_ + kh * HD_;
        __nv_bfloat16* vhp = vh + ((size_t)kh * TT + t) * HD_;
        __nv_bfloat16* vlp = vl + ((size_t)kh * TT + t) * HD_;
        float a = p[i], b = p[i + 64];
        __nv_bfloat16 ha = __float2bfloat16(a), hb = __float2bfloat16(b);
        vhp[i] = ha;
        vhp[i + 64] = hb;
        vlp[i] = __float2bfloat16(a - __bfloat162float(ha));
        vlp[i + 64] = __float2bfloat16(b - __bfloat162float(hb));
    }
}

// ---------------------------------------------------------------------------
// Tensor-core causal GQA flash attention, error-compensated PV.
// CTA: 128 queries x 1 head; 8 warps, warp = 16 query rows (softmax warp-local).
// K-tiles of 64, 2-stage cp.async pipeline for K+Vh+Vl. Output: bf16 hi/lo.
// PV = ph*vh + pl*vh + ph*vl  (3-term bf16).
// ---------------------------------------------------------------------------
#define AKV_STRIDE 49152     // K 16K + Vh 16K + Vl 16K
#define ATTN_SMEM  (32768 + 2 * AKV_STRIDE + 1024)

__global__ __launch_bounds__(256, 1) void attn_mma(
    const __nv_bfloat16* __restrict__ qb, const __nv_bfloat16* __restrict__ kb,
    const __nv_bfloat16* __restrict__ vhg, const __nv_bfloat16* __restrict__ vlg,
    const int* __restrict__ pos,
    __nv_bfloat16* __restrict__ oh, __nv_bfloat16* __restrict__ ol)
{
    extern __shared__ char smem[];
    const int h   = blockIdx.y;
    const int qt  = gridDim.x - 1 - blockIdx.x;   // heavy tiles first
    const int q0  = qt * 128;
    const int kvh = h >> 2;
    const int tid = threadIdx.x, wid = tid >> 5, lane = tid & 31;

    const uint32_t dyn = smem_u32(smem);
    const uint32_t Qb  = (dyn + 1023) & ~1023u;
    const uint32_t KVb = Qb + 32768;

    const __nv_bfloat16* Qg = qb + ((size_t)h * TT + q0) * HD_;
    const __nv_bfloat16* Kg = kb + (size_t)kvh * TT * HD_;
    const __nv_bfloat16* Vh = vhg + (size_t)kvh * TT * HD_;
    const __nv_bfloat16* Vl = vlg + (size_t)kvh * TT * HD_;

    // Q tile: 128 rows x 256B, swizzled
    for (int i = tid; i < 2048; i += 256) {
        int row = i >> 4, cc = i & 15;
        uint32_t off = (uint32_t)row * 256 + (uint32_t)((cc * 16) ^ ((row & 7) << 4));
        cp16(Qb + off, (const char*)Qg + (size_t)row * 256 + cc * 16);
    }
    // stage 0: K,Vh,Vl tile 0
    for (int i = tid; i < 1024; i += 256) {
        int row = i >> 4, cc = i & 15;
        uint32_t off = (uint32_t)row * 256 + (uint32_t)((cc * 16) ^ ((row & 7) << 4));
        cp16(KVb + off,         (const char*)Kg + (size_t)row * 256 + cc * 16);
        cp16(KVb + 16384 + off, (const char*)Vh + (size_t)row * 256 + cc * 16);
        cp16(KVb + 32768 + off, (const char*)Vl + (size_t)row * 256 + cc * 16);
    }
    CP_COMMIT();

    const int r0g = q0 + wid * 16 + (lane >> 2);
    const int pq0 = pos[r0g], pq1 = pos[r0g + 8];

    float m0 = -1e30f, m1 = -1e30f, l0 = 0.f, l1 = 0.f;
    float o_acc[16][4];
#pragma unroll
    for (int i = 0; i < 16; i++)
#pragma unroll
        for (int j = 0; j < 4; j++) o_acc[i][j] = 0.f;

    uint32_t qfrag[8][4];
    const float CSC = 0.12751661970323393f;   // (1/sqrt(128)) * log2(e)

    const int ntile = 2 * qt + 2;
    for (int kt = 0; kt < ntile; kt++) {
        CP_WAIT0();
        __syncthreads();
        const uint32_t cur = KVb + (uint32_t)(kt & 1) * AKV_STRIDE;
        if (kt + 1 < ntile) {
            const int s0n = (kt + 1) * 64;
            const uint32_t nb = KVb + (uint32_t)((kt + 1) & 1) * AKV_STRIDE;
            for (int i = tid; i < 1024; i += 256) {
                int row = i >> 4, cc = i & 15;
                uint32_t off = (uint32_t)row * 256 + (uint32_t)((cc * 16) ^ ((row & 7) << 4));
                cp16(nb + off,         (const char*)(Kg + (size_t)(s0n + row) * HD_) + cc * 16);
                cp16(nb + 16384 + off, (const char*)(Vh + (size_t)(s0n + row) * HD_) + cc * 16);
                cp16(nb + 32768 + off, (const char*)(Vl + (size_t)(s0n + row) * HD_) + cc * 16);
            }
            CP_COMMIT();
        }
        if (kt == 0) {  // Q ready after first wait; loop-invariant fragments
            const uint32_t qrow = (uint32_t)(wid * 16 + (lane & 15));
#pragma unroll
            for (int ks = 0; ks < 8; ks++) {
                uint32_t off = qrow * 256 +
                    (uint32_t)(((ks * 32) + ((lane >> 4) * 16)) ^ ((qrow & 7) << 4));
                LDSM4(qfrag[ks], Qb + off);
            }
        }

        // ---- S = Q K^T (warp: 16 rows x 64 keys) ----
        float sa[8][4];
#pragma unroll
        for (int i = 0; i < 8; i++)
#pragma unroll
            for (int j = 0; j < 4; j++) sa[i][j] = 0.f;
        const uint32_t krow = (uint32_t)((lane & 7) + ((lane >> 4) & 1) * 8);
        const uint32_t kch  = (uint32_t)(((lane >> 3) & 1) * 16);
#pragma unroll
        for (int ks = 0; ks < 8; ks++) {
            uint32_t kf[4][4];
#pragma unroll
            for (int ng = 0; ng < 4; ng++) {
                uint32_t row = ng * 16 + krow;
                uint32_t off = row * 256 + (uint32_t)((ks * 32 + kch) ^ ((row & 7) << 4));
                LDSM4(kf[ng], cur + off);
            }
#pragma unroll
            for (int ng = 0; ng < 4; ng++) {
                MMA_BF16(sa[2 * ng],     qfrag[ks], kf[ng][0], kf[ng][1]);
                MMA_BF16(sa[2 * ng + 1], qfrag[ks], kf[ng][2], kf[ng][3]);
            }
        }

        // ---- scale (+mask) into log2 domain ----
        const int s0 = kt * 64;
        float e[8][4];
        if (kt >= ntile - 2) {
#pragma unroll
            for (int nt = 0; nt < 8; nt++) {
                int c0 = s0 + nt * 8 + (lane & 3) * 2;
                int pk0 = pos[c0], pk1 = pos[c0 + 1];
                e[nt][0] = (pk0 > pq0) ? -1e30f : sa[nt][0] * CSC;
                e[nt][1] = (pk1 > pq0) ? -1e30f : sa[nt][1] * CSC;
                e[nt][2] = (pk0 > pq1) ? -1e30f : sa[nt][2] * CSC;
                e[nt][3] = (pk1 > pq1) ? -1e30f : sa[nt][3] * CSC;
            }
        } else {
#pragma unroll
            for (int nt = 0; nt < 8; nt++)
#pragma unroll
                for (int j = 0; j < 4; j++) e[nt][j] = sa[nt][j] * CSC;
        }

        // ---- online softmax (warp-local, quad shuffles) ----
        float mx0 = -1e30f, mx1 = -1e30f;
#pragma unroll
        for (int nt = 0; nt < 8; nt++) {
            mx0 = fmaxf(mx0, fmaxf(e[nt][0], e[nt][1]));
            mx1 = fmaxf(mx1, fmaxf(e[nt][2], e[nt][3]));
        }
        mx0 = fmaxf(mx0, __shfl_xor_sync(0xffffffffu, mx0, 1));
        mx0 = fmaxf(mx0, __shfl_xor_sync(0xffffffffu, mx0, 2));
        mx1 = fmaxf(mx1, __shfl_xor_sync(0xffffffffu, mx1, 1));
        mx1 = fmaxf(mx1, __shfl_xor_sync(0xffffffffu, mx1, 2));
        const float nm0 = fmaxf(m0, mx0), nm1 = fmaxf(m1, mx1);
        const float al0 = ex2(m0 - nm0), al1 = ex2(m1 - nm1);
        m0 = nm0; m1 = nm1;

        uint32_t pfh[4][4], pfl[4][4];
        float sum0 = 0.f, sum1 = 0.f;
#pragma unroll
        for (int j = 0; j < 4; j++) {
            float pa0 = ex2(e[2 * j][0] - m0),     pa1 = ex2(e[2 * j][1] - m0);
            float pa2 = ex2(e[2 * j][2] - m1),     pa3 = ex2(e[2 * j][3] - m1);
            float pb0 = ex2(e[2 * j + 1][0] - m0), pb1 = ex2(e[2 * j + 1][1] - m0);
            float pb2 = ex2(e[2 * j + 1][2] - m1), pb3 = ex2(e[2 * j + 1][3] - m1);
            sum0 += pa0 + pa1 + pb0 + pb1;
            sum1 += pa2 + pa3 + pb2 + pb3;
            split_pack(pa0, pa1, pfh[j][0], pfl[j][0]);
            split_pack(pa2, pa3, pfh[j][1], pfl[j][1]);
            split_pack(pb0, pb1, pfh[j][2], pfl[j][2]);
            split_pack(pb2, pb3, pfh[j][3], pfl[j][3]);
        }
        sum0 += __shfl_xor_sync(0xffffffffu, sum0, 1);
        sum0 += __shfl_xor_sync(0xffffffffu, sum0, 2);
        sum1 += __shfl_xor_sync(0xffffffffu, sum1, 1);
        sum1 += __shfl_xor_sync(0xffffffffu, sum1, 2);
        l0 = l0 * al0 + sum0;
        l1 = l1 * al1 + sum1;

#pragma unroll
        for (int dt = 0; dt < 16; dt++) {
            o_acc[dt][0] *= al0; o_acc[dt][1] *= al0;
            o_acc[dt][2] *= al1; o_acc[dt][3] *= al1;
        }

        // ---- O += ph*Vh + pl*Vh + ph*Vl  (V via ldmatrix.trans) ----
        const uint32_t vch = (uint32_t)((lane >> 4) * 16);
#pragma unroll
        for (int j = 0; j < 4; j++) {
            const uint32_t vrow = (uint32_t)(j * 16 + (lane & 15));
#pragma unroll
            for (int dt = 0; dt < 8; dt++) {
                uint32_t off = vrow * 256 + (uint32_t)((dt * 32 + vch) ^ ((vrow & 7) << 4));
                uint32_t vfh[4], vfl[4];
                LDSM4T(vfh, cur + 16384 + off);
                LDSM4T(vfl, cur + 32768 + off);
                MMA_BF16(o_acc[2 * dt],     pfh[j], vfh[0], vfh[1]);
                MMA_BF16(o_acc[2 * dt],     pfl[j], vfh[0], vfh[1]);
                MMA_BF16(o_acc[2 * dt],     pfh[j], vfl[0], vfl[1]);
                MMA_BF16(o_acc[2 * dt + 1], pfh[j], vfh[2], vfh[3]);
                MMA_BF16(o_acc[2 * dt + 1], pfl[j], vfh[2], vfh[3]);
                MMA_BF16(o_acc[2 * dt + 1], pfh[j], vfl[2], vfl[3]);
            }
        }
    }

    // ---- epilogue: normalize, split hi/lo, store ----
    const float inv0 = 1.f / l0, inv1 = 1.f / l1;
    const int row0 = q0 + wid * 16 + (lane >> 2);
#pragma unroll
    for (int nt = 0; nt < 16; nt++) {
        const int col = h * HD_ + nt * 8 + (lane & 3) * 2;
        float v0 = o_acc[nt][0] * inv0, v1 = o_acc[nt][1] * inv0;
        float v2 = o_acc[nt][2] * inv1, v3 = o_acc[nt][3] * inv1;
        uint32_t hw0, lw0, hw1, lw1;
        split_pack(v0, v1, hw0, lw0);
        split_pack(v2, v3, hw1, lw1);
        size_t i0 = (size_t)row0 * HID_ + col;
        size_t i1 = (size_t)(row0 + 8) * HID_ + col;
        *(uint32_t*)&oh[i0] = hw0;
        *(uint32_t*)&oh[i1] = hw1;
        *(uint32_t*)&ol[i0] = lw0;
        *(uint32_t*)&ol[i1] = lw1;
    }
}

// ---------------------------------------------------------------------------
extern "C" void kernel_launch(void* const* d_in, const int* in_sizes, int n_in,
                              void* d_out, int out_size)
{
    const float* hidden = (const float*)d_in[0];   // [T, HID]
    const float* w_qkv  = (const float*)d_in[1];   // [HID, 3072]
    const float* w_o    = (const float*)d_in[2];   // [HID, HID]
    const int*   posp   = (const int*)d_in[3];     // [T]
    float* out = (float*)d_out;                    // [T, HID]

    float* qkvp;  cudaGetSymbolAddress((void**)&qkvp, g_qkv);
    __nv_bfloat16 *hh, *hl, *wqh, *wql, *woh, *wol, *ah, *al, *qbp, *kbp, *vhp, *vlp;
    cudaGetSymbolAddress((void**)&hh, g_hh);
    cudaGetSymbolAddress((void**)&hl, g_hl);
    cudaGetSymbolAddress((void**)&wqh, g_wqh);
    cudaGetSymbolAddress((void**)&wql, g_wql);
    cudaGetSymbolAddress((void**)&woh, g_woh);
    cudaGetSymbolAddress((void**)&wol, g_wol);
    cudaGetSymbolAddress((void**)&ah, g_ah);
    cudaGetSymbolAddress((void**)&al, g_al);
    cudaGetSymbolAddress((void**)&qbp, g_qb);
    cudaGetSymbolAddress((void**)&kbp, g_kb);
    cudaGetSymbolAddress((void**)&vhp, g_vh);
    cudaGetSymbolAddress((void**)&vlp, g_vl);

    cudaFuncSetAttribute((const void*)gemm_mma,
                         cudaFuncAttributeMaxDynamicSharedMemorySize, GEMM_SMEM);
    cudaFuncSetAttribute((const void*)attn_mma,
                         cudaFuncAttributeMaxDynamicSharedMemorySize, ATTN_SMEM);

    // 0) convert operands to bf16 hi/lo
    split_bf16<<<TT * HID_ / 1024, 256>>>(hidden, hh, hl);
    transpose_split<<<dim3(QKVN / 32, HID_ / 32), dim3(32, 8)>>>(w_qkv, wqh, wql, HID_, QKVN);
    transpose_split<<<dim3(HID_ / 32, HID_ / 32), dim3(32, 8)>>>(w_o, woh, wol, HID_, HID_);

    // 1) qkv = hidden @ w_qkv (mma.sync, 3x-bf16)
    gemm_mma<<<dim3(QKVN / 128, TT / 128), 256, GEMM_SMEM>>>(hh, hl, wqh, wql, qkvp, QKVN, HID_);

    // 2) RoPE + bf16 convert (head-major); V split hi/lo
    rope_convert<<<dim3(TT / 4, NH + 2 * NKV), dim3(64, 4)>>>(qkvp, posp, qbp, kbp, vhp, vlp);

    // 3) tensor-core flash attention, compensated PV (writes bf16 hi/lo)
    attn_mma<<<dim3(TT / 128, NH), 256, ATTN_SMEM>>>(qbp, kbp, vhp, vlp, posp, ah, al);

    // 4) out = attn @ w_o (mma.sync, 3x-bf16)
    gemm_mma<<<dim3(HID_ / 128, TT / 128), 256, GEMM_SMEM>>>(ah, al, woh, wol, out, HID_, HID_);
}

// round 14
// speedup vs baseline: 3.9094x; 1.1001x over previous
#include <cuda_runtime.h>
#include <cuda_bf16.h>
#include <cuda_fp16.h>
#include <stdint.h>
#include <math.h>

#define TT   2048
#define HID_ 2048
#define NH   16
#define NKV  4
#define HD_  128
#define QKVN ((NH + 2 * NKV) * HD_)   // 3072
#define GRP  (NH / NKV)               // 4

// ---------------------------------------------------------------------------
// Scratch (allocation-free rule: static device globals)
// ---------------------------------------------------------------------------
__device__ float g_qkv[TT * QKVN];                          // qkv projection (fp32)
__device__ __align__(256) __nv_bfloat16 g_hh[TT * HID_];    // hidden hi
__device__ __align__(256) __nv_bfloat16 g_hl[TT * HID_];    // hidden lo
__device__ __align__(256) __nv_bfloat16 g_wqh[QKVN * HID_]; // w_qkv^T hi [N][K]
__device__ __align__(256) __nv_bfloat16 g_wql[QKVN * HID_]; // w_qkv^T lo
__device__ __align__(256) __nv_bfloat16 g_woh[HID_ * HID_]; // w_o^T hi
__device__ __align__(256) __nv_bfloat16 g_wol[HID_ * HID_]; // w_o^T lo
__device__ __align__(256) __nv_bfloat16 g_ah[TT * HID_];    // attn out hi
__device__ __align__(256) __nv_bfloat16 g_al[TT * HID_];    // attn out lo
__device__ __align__(256) __half g_qb[NH * TT * HD_];       // rope'd Q fp16 [h][t][d]
__device__ __align__(256) __half g_kb[NKV * TT * HD_];      // rope'd K fp16 [kh][t][d]
__device__ __align__(256) __half g_vb[NKV * TT * HD_];      // V fp16 [kh][t][d]

// ---------------------------------------------------------------------------
// PTX helpers (baseline ISA only: ldmatrix / mma.sync / cp.async)
// ---------------------------------------------------------------------------
__device__ __forceinline__ uint32_t smem_u32(const void* p) {
    uint32_t a;
    asm("{ .reg .u64 t; cvta.to.shared.u64 t, %1; cvt.u32.u64 %0, t; }" : "=r"(a) : "l"(p));
    return a;
}
#define LDSM4(r, addr) \
    asm volatile("ldmatrix.sync.aligned.m8n8.x4.shared.b16 {%0,%1,%2,%3}, [%4];" \
        : "=r"((r)[0]), "=r"((r)[1]), "=r"((r)[2]), "=r"((r)[3]) : "r"(addr))
#define LDSM4T(r, addr) \
    asm volatile("ldmatrix.sync.aligned.m8n8.x4.trans.shared.b16 {%0,%1,%2,%3}, [%4];" \
        : "=r"((r)[0]), "=r"((r)[1]), "=r"((r)[2]), "=r"((r)[3]) : "r"(addr))
#define MMA_BF16(d, a, b0, b1) \
    asm volatile("mma.sync.aligned.m16n8k16.row.col.f32.bf16.bf16.f32 " \
        "{%0,%1,%2,%3},{%4,%5,%6,%7},{%8,%9},{%0,%1,%2,%3};" \
        : "+f"((d)[0]), "+f"((d)[1]), "+f"((d)[2]), "+f"((d)[3]) \
        : "r"((a)[0]), "r"((a)[1]), "r"((a)[2]), "r"((a)[3]), "r"(b0), "r"(b1))
#define MMA_F16(d, a, b0, b1) \
    asm volatile("mma.sync.aligned.m16n8k16.row.col.f32.f16.f16.f32 " \
        "{%0,%1,%2,%3},{%4,%5,%6,%7},{%8,%9},{%0,%1,%2,%3};" \
        : "+f"((d)[0]), "+f"((d)[1]), "+f"((d)[2]), "+f"((d)[3]) \
        : "r"((a)[0]), "r"((a)[1]), "r"((a)[2]), "r"((a)[3]), "r"(b0), "r"(b1))
__device__ __forceinline__ void cp16(uint32_t dst, const void* src) {
    asm volatile("cp.async.cg.shared.global [%0], [%1], 16;" :: "r"(dst), "l"(src));
}
#define CP_COMMIT() asm volatile("cp.async.commit_group;" ::: "memory")
#define CP_WAIT0()  asm volatile("cp.async.wait_group 0;" ::: "memory")
__device__ __forceinline__ float ex2(float x) {
    float r;
    asm("ex2.approx.ftz.f32 %0, %1;" : "=f"(r) : "f"(x));
    return r;
}
__device__ __forceinline__ uint32_t packbf(float a, float b) {
    __nv_bfloat162 t = __floats2bfloat162_rn(a, b);
    return reinterpret_cast<uint32_t&>(t);
}
__device__ __forceinline__ uint32_t packh(float a, float b) {
    __half2 t = __floats2half2_rn(a, b);
    return reinterpret_cast<uint32_t&>(t);
}
// pack hi(bf16) of (a,b) and lo residual pair
__device__ __forceinline__ void split_pack(float a, float b, uint32_t& h, uint32_t& l) {
    __nv_bfloat16 ha = __float2bfloat16(a), hb = __float2bfloat16(b);
    h = (uint32_t)reinterpret_cast<unsigned short&>(ha) |
        ((uint32_t)reinterpret_cast<unsigned short&>(hb) << 16);
    l = packbf(a - __bfloat162float(ha), b - __bfloat162float(hb));
}

// ---------------------------------------------------------------------------
// fp32 -> bf16 hi/lo split (hidden_states)
// ---------------------------------------------------------------------------
__global__ void split_bf16(const float* __restrict__ x,
                           __nv_bfloat16* __restrict__ hi,
                           __nv_bfloat16* __restrict__ lo)
{
    int i = (blockIdx.x * 256 + threadIdx.x) * 4;
    float4 v = *(const float4*)&x[i];
    uint2 hp, lp;
    split_pack(v.x, v.y, hp.x, lp.x);
    split_pack(v.z, v.w, hp.y, lp.y);
    *(uint2*)&hi[i] = hp;
    *(uint2*)&lo[i] = lp;
}

// ---------------------------------------------------------------------------
// Weight transpose + split: W[K][N] fp32 -> Wt_hi/Wt_lo [N][K] bf16
// ---------------------------------------------------------------------------
__global__ void transpose_split(const float* __restrict__ W,
                                __nv_bfloat16* __restrict__ Th,
                                __nv_bfloat16* __restrict__ Tl,
                                int K, int N)
{
    __shared__ float sm[32][33];
    const int n0 = blockIdx.x * 32, k0 = blockIdx.y * 32;
    const int tx = threadIdx.x, ty = threadIdx.y;   // 32 x 8
#pragma unroll
    for (int i = 0; i < 4; i++)
        sm[ty + i * 8][tx] = W[(size_t)(k0 + ty + i * 8) * N + n0 + tx];
    __syncthreads();
#pragma unroll
    for (int i = 0; i < 4; i++) {
        float v = sm[tx][ty + i * 8];
        __nv_bfloat16 h = __float2bfloat16(v);
        __nv_bfloat16 l = __float2bfloat16(v - __bfloat162float(h));
        size_t o = (size_t)(n0 + ty + i * 8) * K + k0 + tx;
        Th[o] = h;
        Tl[o] = l;
    }
}

// ---------------------------------------------------------------------------
// mma.sync GEMM: C[M,N] = (Ah+Al)[M,K] @ (Bh+Bl)^T, B stored [N][K] K-major.
// 3-term bf16. CTA 128x128, BK=64, 2-stage cp.async. Warp 64x32, m16n8k16.
// ---------------------------------------------------------------------------
#define STG_AH 0
#define STG_AL 16384
#define STG_BH 32768
#define STG_BL 49152
#define STG_STRIDE 65536
#define GEMM_SMEM (2 * STG_STRIDE + 1024)

__device__ __forceinline__ void issue_tile_loads(
    const __nv_bfloat16* __restrict__ g, uint32_t sdst, int K, int tid)
{
#pragma unroll
    for (int i = 0; i < 4; i++) {
        int id = tid + i * 256;
        int row = id >> 3, cc = id & 7;
        uint32_t off = row * 128 + ((cc * 16) ^ ((row & 7) << 4));
        cp16(sdst + off, g + (size_t)row * K + cc * 8);
    }
}

__global__ __launch_bounds__(256, 1) void gemm_mma(
    const __nv_bfloat16* __restrict__ Ah, const __nv_bfloat16* __restrict__ Al,
    const __nv_bfloat16* __restrict__ Bh, const __nv_bfloat16* __restrict__ Bl,
    float* __restrict__ C, int N, int K)
{
    extern __shared__ char smem[];
    const int tid  = threadIdx.x;
    const int wid  = tid >> 5;
    const int lane = tid & 31;
    const int m0 = blockIdx.y * 128;
    const int n0 = blockIdx.x * 128;
    const int m0w = (wid >> 2) * 64;
    const int n0w = (wid & 3) * 32;

    const uint32_t dyn = smem_u32(smem);
    const uint32_t tbase = (dyn + 1023) & ~1023u;

    const __nv_bfloat16* gAh = Ah + (size_t)m0 * K;
    const __nv_bfloat16* gAl = Al + (size_t)m0 * K;
    const __nv_bfloat16* gBh = Bh + (size_t)n0 * K;
    const __nv_bfloat16* gBl = Bl + (size_t)n0 * K;

    float acc[4][4][4];
#pragma unroll
    for (int i = 0; i < 4; i++)
#pragma unroll
        for (int j = 0; j < 4; j++)
#pragma unroll
            for (int k = 0; k < 4; k++) acc[i][j][k] = 0.f;

    const int lrowA = lane & 15;
    const uint32_t aRow = (uint32_t)(m0w + lrowA) * 128;
    const uint32_t xA = (uint32_t)(lrowA & 7) << 4;
    const uint32_t akh = ((uint32_t)lane >> 4) * 16;
    const int nrow = n0w + (lane & 7) + ((lane >> 4) & 1) * 8;
    const uint32_t bRow = (uint32_t)nrow * 128;
    const uint32_t xB = (uint32_t)(lane & 7) << 4;
    const uint32_t bkh = (((uint32_t)lane >> 3) & 1) * 16;

    issue_tile_loads(gAh, tbase + STG_AH, K, tid);
    issue_tile_loads(gAl, tbase + STG_AL, K, tid);
    issue_tile_loads(gBh, tbase + STG_BH, K, tid);
    issue_tile_loads(gBl, tbase + STG_BL, K, tid);
    CP_COMMIT();

    const int nchunk = K >> 6;
    for (int c = 0; c < nchunk; c++) {
        CP_WAIT0();
        __syncthreads();
        if (c + 1 < nchunk) {
            const uint32_t st = tbase + ((c + 1) & 1) * STG_STRIDE;
            const int k0 = (c + 1) << 6;
            issue_tile_loads(gAh + k0, st + STG_AH, K, tid);
            issue_tile_loads(gAl + k0, st + STG_AL, K, tid);
            issue_tile_loads(gBh + k0, st + STG_BH, K, tid);
            issue_tile_loads(gBl + k0, st + STG_BL, K, tid);
            CP_COMMIT();
        }
        const uint32_t sc = tbase + (c & 1) * STG_STRIDE;
        const uint32_t sAh = sc + STG_AH, sAl = sc + STG_AL;
        const uint32_t sBh = sc + STG_BH, sBl = sc + STG_BL;

#pragma unroll
        for (int ks = 0; ks < 4; ks++) {
            const uint32_t akt = ((uint32_t)ks * 32 + akh) ^ xA;
            const uint32_t bkt = ((uint32_t)ks * 32 + bkh) ^ xB;
            uint32_t ah[4][4], al[4][4], bh[2][4], bl[2][4];
#pragma unroll
            for (int mt = 0; mt < 4; mt++) {
                uint32_t ao = aRow + mt * 2048 + akt;
                LDSM4(ah[mt], sAh + ao);
                LDSM4(al[mt], sAl + ao);
            }
#pragma unroll
            for (int pr = 0; pr < 2; pr++) {
                uint32_t bo = bRow + pr * 2048 + bkt;
                LDSM4(bh[pr], sBh + bo);
                LDSM4(bl[pr], sBl + bo);
            }
#pragma unroll
            for (int mt = 0; mt < 4; mt++) {
#pragma unroll
                for (int nt = 0; nt < 4; nt++) {
                    const int pr = nt >> 1, hf = (nt & 1) * 2;
                    MMA_BF16(acc[mt][nt], ah[mt], bh[pr][hf], bh[pr][hf + 1]);
                    MMA_BF16(acc[mt][nt], ah[mt], bl[pr][hf], bl[pr][hf + 1]);
                    MMA_BF16(acc[mt][nt], al[mt], bh[pr][hf], bh[pr][hf + 1]);
                }
            }
        }
        __syncthreads();
    }

    const int rr = lane >> 2, rc = (lane & 3) * 2;
#pragma unroll
    for (int mt = 0; mt < 4; mt++) {
        const int row = m0 + m0w + mt * 16 + rr;
#pragma unroll
        for (int nt = 0; nt < 4; nt++) {
            const int col = n0 + n0w + nt * 8 + rc;
            *(float2*)&C[(size_t)row * N + col] = make_float2(acc[mt][nt][0], acc[mt][nt][1]);
            *(float2*)&C[(size_t)(row + 8) * N + col] = make_float2(acc[mt][nt][2], acc[mt][nt][3]);
        }
    }
}

// ---------------------------------------------------------------------------
// RoPE + convert: q/k rope'd -> fp16; v -> fp16; head-major layouts
// grid (T/4, NH+2*NKV), block (64,4)
// ---------------------------------------------------------------------------
__global__ void rope_convert(const float* __restrict__ qkv,
                             const int* __restrict__ pos,
                             __half* __restrict__ qb,
                             __half* __restrict__ kb,
                             __half* __restrict__ vb)
{
    const int t = blockIdx.x * 4 + threadIdx.y;
    const int head = blockIdx.y;              // 0..23
    const int i = threadIdx.x;                // 0..63

    if (head < NH + NKV) {
        const float* p = qkv + (size_t)t * QKVN + head * HD_;
        double invf = exp(-log(1000000.0) * (2.0 * (double)i / (double)HD_));
        double fr = (double)pos[t] * invf;
        float c = (float)cos(fr);
        float s = (float)sin(fr);
        float x1 = p[i];
        float x2 = p[i + HD_ / 2];
        float y1 = x1 * c - x2 * s;
        float y2 = x2 * c + x1 * s;
        if (head < NH) {
            __half* q = qb + ((size_t)head * TT + t) * HD_;
            q[i] = __float2half_rn(y1);
            q[i + 64] = __float2half_rn(y2);
        } else {
            __half* k = kb + ((size_t)(head - NH) * TT + t) * HD_;
            k[i] = __float2half_rn(y1);
            k[i + 64] = __float2half_rn(y2);
        }
    } else {
        const int kh = head - NH - NKV;
        const float* p = qkv + (size_t)t * QKVN + HID_ + NKV * HD_ + kh * HD_;
        __half* v = vb + ((size_t)kh * TT + t) * HD_;
        v[i] = __float2half_rn(p[i]);
        v[i + 64] = __float2half_rn(p[i + 64]);
    }
}

// ---------------------------------------------------------------------------
// Tensor-core causal GQA flash attention, fp16 operands, fp32 accumulate.
// CTA: 128 queries x 1 head; 8 warps, warp = 16 query rows (softmax warp-local).
// K-tiles of 64, 2-stage cp.async pipeline for K+V. Output: bf16 hi/lo.
// 1D grid, heavy q-tiles first across all heads (LPT-style greedy).
// ---------------------------------------------------------------------------
#define AKV_STRIDE 32768     // K 16K + V 16K
#define ATTN_SMEM  (32768 + 2 * AKV_STRIDE + 1024)

__global__ __launch_bounds__(256, 1) void attn_mma(
    const __half* __restrict__ qb, const __half* __restrict__ kb,
    const __half* __restrict__ vbg, const int* __restrict__ pos,
    __nv_bfloat16* __restrict__ oh, __nv_bfloat16* __restrict__ ol)
{
    extern __shared__ char smem[];
    const int bid = blockIdx.x;
    const int h   = bid & (NH - 1);
    const int qt  = (TT / 128 - 1) - (bid >> 4);   // heavy tiles first
    const int q0  = qt * 128;
    const int kvh = h >> 2;
    const int tid = threadIdx.x, wid = tid >> 5, lane = tid & 31;

    const uint32_t dyn = smem_u32(smem);
    const uint32_t Qb  = (dyn + 1023) & ~1023u;
    const uint32_t KVb = Qb + 32768;

    const __half* Qg = qb + ((size_t)h * TT + q0) * HD_;
    const __half* Kg = kb + (size_t)kvh * TT * HD_;
    const __half* Vg = vbg + (size_t)kvh * TT * HD_;

    // Q tile: 128 rows x 256B, swizzled
    for (int i = tid; i < 2048; i += 256) {
        int row = i >> 4, cc = i & 15;
        uint32_t off = (uint32_t)row * 256 + (uint32_t)((cc * 16) ^ ((row & 7) << 4));
        cp16(Qb + off, (const char*)Qg + (size_t)row * 256 + cc * 16);
    }
    // stage 0: K,V tile 0
    for (int i = tid; i < 1024; i += 256) {
        int row = i >> 4, cc = i & 15;
        uint32_t off = (uint32_t)row * 256 + (uint32_t)((cc * 16) ^ ((row & 7) << 4));
        cp16(KVb + off,         (const char*)Kg + (size_t)row * 256 + cc * 16);
        cp16(KVb + 16384 + off, (const char*)Vg + (size_t)row * 256 + cc * 16);
    }
    CP_COMMIT();

    const int r0g = q0 + wid * 16 + (lane >> 2);
    const int pq0 = pos[r0g], pq1 = pos[r0g + 8];

    float m0 = -1e30f, m1 = -1e30f, l0 = 0.f, l1 = 0.f;
    float o_acc[16][4];
#pragma unroll
    for (int i = 0; i < 16; i++)
#pragma unroll
        for (int j = 0; j < 4; j++) o_acc[i][j] = 0.f;

    uint32_t qfrag[8][4];
    const float CSC = 0.12751661970323393f;   // (1/sqrt(128)) * log2(e)

    const int ntile = 2 * qt + 2;
    for (int kt = 0; kt < ntile; kt++) {
        CP_WAIT0();
        __syncthreads();
        const uint32_t cur = KVb + (uint32_t)(kt & 1) * AKV_STRIDE;
        if (kt + 1 < ntile) {
            const int s0n = (kt + 1) * 64;
            const uint32_t nb = KVb + (uint32_t)((kt + 1) & 1) * AKV_STRIDE;
            for (int i = tid; i < 1024; i += 256) {
                int row = i >> 4, cc = i & 15;
                uint32_t off = (uint32_t)row * 256 + (uint32_t)((cc * 16) ^ ((row & 7) << 4));
                cp16(nb + off,         (const char*)(Kg + (size_t)(s0n + row) * HD_) + cc * 16);
                cp16(nb + 16384 + off, (const char*)(Vg + (size_t)(s0n + row) * HD_) + cc * 16);
            }
            CP_COMMIT();
        }
        if (kt == 0) {  // Q ready after first wait; loop-invariant fragments
            const uint32_t qrow = (uint32_t)(wid * 16 + (lane & 15));
#pragma unroll
            for (int ks = 0; ks < 8; ks++) {
                uint32_t off = qrow * 256 +
                    (uint32_t)(((ks * 32) + ((lane >> 4) * 16)) ^ ((qrow & 7) << 4));
                LDSM4(qfrag[ks], Qb + off);
            }
        }

        // ---- S = Q K^T (warp: 16 rows x 64 keys) ----
        float sa[8][4];
#pragma unroll
        for (int i = 0; i < 8; i++)
#pragma unroll
            for (int j = 0; j < 4; j++) sa[i][j] = 0.f;
        const uint32_t krow = (uint32_t)((lane & 7) + ((lane >> 4) & 1) * 8);
        const uint32_t kch  = (uint32_t)(((lane >> 3) & 1) * 16);
#pragma unroll
        for (int ks = 0; ks < 8; ks++) {
            uint32_t kf[4][4];
#pragma unroll
            for (int ng = 0; ng < 4; ng++) {
                uint32_t row = ng * 16 + krow;
                uint32_t off = row * 256 + (uint32_t)((ks * 32 + kch) ^ ((row & 7) << 4));
                LDSM4(kf[ng], cur + off);
            }
#pragma unroll
            for (int ng = 0; ng < 4; ng++) {
                MMA_F16(sa[2 * ng],     qfrag[ks], kf[ng][0], kf[ng][1]);
                MMA_F16(sa[2 * ng + 1], qfrag[ks], kf[ng][2], kf[ng][3]);
            }
        }

        // ---- scale (+mask) into log2 domain ----
        const int s0 = kt * 64;
        float e[8][4];
        if (kt >= ntile - 2) {
#pragma unroll
            for (int nt = 0; nt < 8; nt++) {
                int c0 = s0 + nt * 8 + (lane & 3) * 2;
                int pk0 = pos[c0], pk1 = pos[c0 + 1];
                e[nt][0] = (pk0 > pq0) ? -1e30f : sa[nt][0] * CSC;
                e[nt][1] = (pk1 > pq0) ? -1e30f : sa[nt][1] * CSC;
                e[nt][2] = (pk0 > pq1) ? -1e30f : sa[nt][2] * CSC;
                e[nt][3] = (pk1 > pq1) ? -1e30f : sa[nt][3] * CSC;
            }
        } else {
#pragma unroll
            for (int nt = 0; nt < 8; nt++)
#pragma unroll
                for (int j = 0; j < 4; j++) e[nt][j] = sa[nt][j] * CSC;
        }

        // ---- online softmax (warp-local, quad shuffles) ----
        float mx0 = -1e30f, mx1 = -1e30f;
#pragma unroll
        for (int nt = 0; nt < 8; nt++) {
            mx0 = fmaxf(mx0, fmaxf(e[nt][0], e[nt][1]));
            mx1 = fmaxf(mx1, fmaxf(e[nt][2], e[nt][3]));
        }
        mx0 = fmaxf(mx0, __shfl_xor_sync(0xffffffffu, mx0, 1));
        mx0 = fmaxf(mx0, __shfl_xor_sync(0xffffffffu, mx0, 2));
        mx1 = fmaxf(mx1, __shfl_xor_sync(0xffffffffu, mx1, 1));
        mx1 = fmaxf(mx1, __shfl_xor_sync(0xffffffffu, mx1, 2));
        const float nm0 = fmaxf(m0, mx0), nm1 = fmaxf(m1, mx1);
        const float al0 = ex2(m0 - nm0), al1 = ex2(m1 - nm1);
        m0 = nm0; m1 = nm1;

        uint32_t pf[4][4];
        float sum0 = 0.f, sum1 = 0.f;
#pragma unroll
        for (int j = 0; j < 4; j++) {
            float pa0 = ex2(e[2 * j][0] - m0),     pa1 = ex2(e[2 * j][1] - m0);
            float pa2 = ex2(e[2 * j][2] - m1),     pa3 = ex2(e[2 * j][3] - m1);
            float pb0 = ex2(e[2 * j + 1][0] - m0), pb1 = ex2(e[2 * j + 1][1] - m0);
            float pb2 = ex2(e[2 * j + 1][2] - m1), pb3 = ex2(e[2 * j + 1][3] - m1);
            sum0 += pa0 + pa1 + pb0 + pb1;
            sum1 += pa2 + pa3 + pb2 + pb3;
            pf[j][0] = packh(pa0, pa1);
            pf[j][1] = packh(pa2, pa3);
            pf[j][2] = packh(pb0, pb1);
            pf[j][3] = packh(pb2, pb3);
        }
        sum0 += __shfl_xor_sync(0xffffffffu, sum0, 1);
        sum0 += __shfl_xor_sync(0xffffffffu, sum0, 2);
        sum1 += __shfl_xor_sync(0xffffffffu, sum1, 1);
        sum1 += __shfl_xor_sync(0xffffffffu, sum1, 2);
        l0 = l0 * al0 + sum0;
        l1 = l1 * al1 + sum1;

        // rescale o_acc (skip when whole warp has alpha == 1: max didn't move)
        if (!__all_sync(0xffffffffu, (al0 == 1.f) && (al1 == 1.f))) {
#pragma unroll
            for (int dt = 0; dt < 16; dt++) {
                o_acc[dt][0] *= al0; o_acc[dt][1] *= al0;
                o_acc[dt][2] *= al1; o_acc[dt][3] *= al1;
            }
        }

        // ---- O += P V  (V via ldmatrix.trans) ----
        const uint32_t vch = (uint32_t)((lane >> 4) * 16);
#pragma unroll
        for (int j = 0; j < 4; j++) {
            const uint32_t vrow = (uint32_t)(j * 16 + (lane & 15));
#pragma unroll
            for (int dt = 0; dt < 8; dt++) {
                uint32_t off = vrow * 256 + (uint32_t)((dt * 32 + vch) ^ ((vrow & 7) << 4));
                uint32_t vf[4];
                LDSM4T(vf, cur + 16384 + off);
                MMA_F16(o_acc[2 * dt],     pf[j], vf[0], vf[1]);
                MMA_F16(o_acc[2 * dt + 1], pf[j], vf[2], vf[3]);
            }
        }
    }

    // ---- epilogue: normalize, split hi/lo, store ----
    const float inv0 = 1.f / l0, inv1 = 1.f / l1;
    const int row0 = q0 + wid * 16 + (lane >> 2);
#pragma unroll
    for (int nt = 0; nt < 16; nt++) {
        const int col = h * HD_ + nt * 8 + (lane & 3) * 2;
        float v0 = o_acc[nt][0] * inv0, v1 = o_acc[nt][1] * inv0;
        float v2 = o_acc[nt][2] * inv1, v3 = o_acc[nt][3] * inv1;
        uint32_t hw0, lw0, hw1, lw1;
        split_pack(v0, v1, hw0, lw0);
        split_pack(v2, v3, hw1, lw1);
        size_t i0 = (size_t)row0 * HID_ + col;
        size_t i1 = (size_t)(row0 + 8) * HID_ + col;
        *(uint32_t*)&oh[i0] = hw0;
        *(uint32_t*)&oh[i1] = hw1;
        *(uint32_t*)&ol[i0] = lw0;
        *(uint32_t*)&ol[i1] = lw1;
    }
}

// ---------------------------------------------------------------------------
extern "C" void kernel_launch(void* const* d_in, const int* in_sizes, int n_in,
                              void* d_out, int out_size)
{
    const float* hidden = (const float*)d_in[0];   // [T, HID]
    const float* w_qkv  = (const float*)d_in[1];   // [HID, 3072]
    const float* w_o    = (const float*)d_in[2];   // [HID, HID]
    const int*   posp   = (const int*)d_in[3];     // [T]
    float* out = (float*)d_out;                    // [T, HID]

    float* qkvp;  cudaGetSymbolAddress((void**)&qkvp, g_qkv);
    __nv_bfloat16 *hh, *hl, *wqh, *wql, *woh, *wol, *ah, *al;
    __half *qbp, *kbp, *vbp;
    cudaGetSymbolAddress((void**)&hh, g_hh);
    cudaGetSymbolAddress((void**)&hl, g_hl);
    cudaGetSymbolAddress((void**)&wqh, g_wqh);
    cudaGetSymbolAddress((void**)&wql, g_wql);
    cudaGetSymbolAddress((void**)&woh, g_woh);
    cudaGetSymbolAddress((void**)&wol, g_wol);
    cudaGetSymbolAddress((void**)&ah, g_ah);
    cudaGetSymbolAddress((void**)&al, g_al);
    cudaGetSymbolAddress((void**)&qbp, g_qb);
    cudaGetSymbolAddress((void**)&kbp, g_kb);
    cudaGetSymbolAddress((void**)&vbp, g_vb);

    cudaFuncSetAttribute((const void*)gemm_mma,
                         cudaFuncAttributeMaxDynamicSharedMemorySize, GEMM_SMEM);
    cudaFuncSetAttribute((const void*)attn_mma,
                         cudaFuncAttributeMaxDynamicSharedMemorySize, ATTN_SMEM);

    // 0) convert operands to bf16 hi/lo
    split_bf16<<<TT * HID_ / 1024, 256>>>(hidden, hh, hl);
    transpose_split<<<dim3(QKVN / 32, HID_ / 32), dim3(32, 8)>>>(w_qkv, wqh, wql, HID_, QKVN);
    transpose_split<<<dim3(HID_ / 32, HID_ / 32), dim3(32, 8)>>>(w_o, woh, wol, HID_, HID_);

    // 1) qkv = hidden @ w_qkv (mma.sync, 3x-bf16)
    gemm_mma<<<dim3(QKVN / 128, TT / 128), 256, GEMM_SMEM>>>(hh, hl, wqh, wql, qkvp, QKVN, HID_);

    // 2) RoPE + fp16 convert (head-major)
    rope_convert<<<dim3(TT / 4, NH + 2 * NKV), dim3(64, 4)>>>(qkvp, posp, qbp, kbp, vbp);

    // 3) tensor-core flash attention, fp16 (writes bf16 hi/lo)
    attn_mma<<<dim3((TT / 128) * NH), 256, ATTN_SMEM>>>(qbp, kbp, vbp, posp, ah, al);

    // 4) out = attn @ w_o (mma.sync, 3x-bf16)
    gemm_mma<<<dim3(HID_ / 128, TT / 128), 256, GEMM_SMEM>>>(ah, al, woh, wol, out, HID_, HID_);
}

// round 15
// speedup vs baseline: 7.5306x; 1.9263x over previous
#include <cuda_runtime.h>
#include <cuda_bf16.h>
#include <cuda_fp16.h>
#include <stdint.h>
#include <math.h>

#define TT   2048
#define HID_ 2048
#define NH   16
#define NKV  4
#define HD_  128
#define QKVN ((NH + 2 * NKV) * HD_)   // 3072
#define GRP  (NH / NKV)               // 4

// ---------------------------------------------------------------------------
// Scratch (allocation-free rule: static device globals)
// ---------------------------------------------------------------------------
__device__ float g_qkv[TT * QKVN];                          // qkv projection (fp32)
__device__ __align__(256) __nv_bfloat16 g_hh[TT * HID_];    // hidden hi
__device__ __align__(256) __nv_bfloat16 g_hl[TT * HID_];    // hidden lo
__device__ __align__(256) __nv_bfloat16 g_wqh[QKVN * HID_]; // w_qkv^T hi [N][K]
__device__ __align__(256) __nv_bfloat16 g_wql[QKVN * HID_]; // w_qkv^T lo
__device__ __align__(256) __nv_bfloat16 g_woh[HID_ * HID_]; // w_o^T hi
__device__ __align__(256) __nv_bfloat16 g_wol[HID_ * HID_]; // w_o^T lo
__device__ __align__(256) __nv_bfloat16 g_ah[TT * HID_];    // attn out hi
__device__ __align__(256) __nv_bfloat16 g_al[TT * HID_];    // attn out lo
__device__ __align__(256) __half g_qb[NH * TT * HD_];       // rope'd Q fp16 [h][t][d]
__device__ __align__(256) __half g_kb[NKV * TT * HD_];      // rope'd K fp16 [kh][t][d]
__device__ __align__(256) __half g_vb[NKV * TT * HD_];      // V fp16 [kh][t][d]

// ---------------------------------------------------------------------------
// PTX helpers (baseline ISA only: ldmatrix / mma.sync / cp.async)
// ---------------------------------------------------------------------------
__device__ __forceinline__ uint32_t smem_u32(const void* p) {
    uint32_t a;
    asm("{ .reg .u64 t; cvta.to.shared.u64 t, %1; cvt.u32.u64 %0, t; }" : "=r"(a) : "l"(p));
    return a;
}
#define LDSM4(r, addr) \
    asm volatile("ldmatrix.sync.aligned.m8n8.x4.shared.b16 {%0,%1,%2,%3}, [%4];" \
        : "=r"((r)[0]), "=r"((r)[1]), "=r"((r)[2]), "=r"((r)[3]) : "r"(addr))
#define LDSM4T(r, addr) \
    asm volatile("ldmatrix.sync.aligned.m8n8.x4.trans.shared.b16 {%0,%1,%2,%3}, [%4];" \
        : "=r"((r)[0]), "=r"((r)[1]), "=r"((r)[2]), "=r"((r)[3]) : "r"(addr))
#define MMA_BF16(d, a, b0, b1) \
    asm volatile("mma.sync.aligned.m16n8k16.row.col.f32.bf16.bf16.f32 " \
        "{%0,%1,%2,%3},{%4,%5,%6,%7},{%8,%9},{%0,%1,%2,%3};" \
        : "+f"((d)[0]), "+f"((d)[1]), "+f"((d)[2]), "+f"((d)[3]) \
        : "r"((a)[0]), "r"((a)[1]), "r"((a)[2]), "r"((a)[3]), "r"(b0), "r"(b1))
#define MMA_F16(d, a, b0, b1) \
    asm volatile("mma.sync.aligned.m16n8k16.row.col.f32.f16.f16.f32 " \
        "{%0,%1,%2,%3},{%4,%5,%6,%7},{%8,%9},{%0,%1,%2,%3};" \
        : "+f"((d)[0]), "+f"((d)[1]), "+f"((d)[2]), "+f"((d)[3]) \
        : "r"((a)[0]), "r"((a)[1]), "r"((a)[2]), "r"((a)[3]), "r"(b0), "r"(b1))
__device__ __forceinline__ void cp16(uint32_t dst, const void* src) {
    asm volatile("cp.async.cg.shared.global [%0], [%1], 16;" :: "r"(dst), "l"(src));
}
#define CP_COMMIT() asm volatile("cp.async.commit_group;" ::: "memory")
#define CP_WAIT0()  asm volatile("cp.async.wait_group 0;" ::: "memory")
__device__ __forceinline__ float ex2(float x) {
    float r;
    asm("ex2.approx.ftz.f32 %0, %1;" : "=f"(r) : "f"(x));
    return r;
}
__device__ __forceinline__ uint32_t packbf(float a, float b) {
    __nv_bfloat162 t = __floats2bfloat162_rn(a, b);
    return reinterpret_cast<uint32_t&>(t);
}
__device__ __forceinline__ uint32_t packh(float a, float b) {
    __half2 t = __floats2half2_rn(a, b);
    return reinterpret_cast<uint32_t&>(t);
}
// pack hi(bf16) of (a,b) and lo residual pair
__device__ __forceinline__ void split_pack(float a, float b, uint32_t& h, uint32_t& l) {
    __nv_bfloat16 ha = __float2bfloat16(a), hb = __float2bfloat16(b);
    h = (uint32_t)reinterpret_cast<unsigned short&>(ha) |
        ((uint32_t)reinterpret_cast<unsigned short&>(hb) << 16);
    l = packbf(a - __bfloat162float(ha), b - __bfloat162float(hb));
}

// ---------------------------------------------------------------------------
// fp32 -> bf16 hi/lo split (hidden_states)
// ---------------------------------------------------------------------------
__global__ void split_bf16(const float* __restrict__ x,
                           __nv_bfloat16* __restrict__ hi,
                           __nv_bfloat16* __restrict__ lo)
{
    int i = (blockIdx.x * 256 + threadIdx.x) * 4;
    float4 v = *(const float4*)&x[i];
    uint2 hp, lp;
    split_pack(v.x, v.y, hp.x, lp.x);
    split_pack(v.z, v.w, hp.y, lp.y);
    *(uint2*)&hi[i] = hp;
    *(uint2*)&lo[i] = lp;
}

// ---------------------------------------------------------------------------
// Weight transpose + split: W[K][N] fp32 -> Wt_hi/Wt_lo [N][K] bf16
// ---------------------------------------------------------------------------
__global__ void transpose_split(const float* __restrict__ W,
                                __nv_bfloat16* __restrict__ Th,
                                __nv_bfloat16* __restrict__ Tl,
                                int K, int N)
{
    __shared__ float sm[32][33];
    const int n0 = blockIdx.x * 32, k0 = blockIdx.y * 32;
    const int tx = threadIdx.x, ty = threadIdx.y;   // 32 x 8
#pragma unroll
    for (int i = 0; i < 4; i++)
        sm[ty + i * 8][tx] = W[(size_t)(k0 + ty + i * 8) * N + n0 + tx];
    __syncthreads();
#pragma unroll
    for (int i = 0; i < 4; i++) {
        float v = sm[tx][ty + i * 8];
        __nv_bfloat16 h = __float2bfloat16(v);
        __nv_bfloat16 l = __float2bfloat16(v - __bfloat162float(h));
        size_t o = (size_t)(n0 + ty + i * 8) * K + k0 + tx;
        Th[o] = h;
        Tl[o] = l;
    }
}

// ---------------------------------------------------------------------------
// mma.sync GEMM: C[M,N] = (Ah+Al)[M,K] @ (Bh+Bl)^T, B stored [N][K] K-major.
// 3-term bf16. CTA 128x128, BK=64, 2-stage cp.async. Warp 64x32, m16n8k16.
// ---------------------------------------------------------------------------
#define STG_AH 0
#define STG_AL 16384
#define STG_BH 32768
#define STG_BL 49152
#define STG_STRIDE 65536
#define GEMM_SMEM (2 * STG_STRIDE + 1024)

__device__ __forceinline__ void issue_tile_loads(
    const __nv_bfloat16* __restrict__ g, uint32_t sdst, int K, int tid)
{
#pragma unroll
    for (int i = 0; i < 4; i++) {
        int id = tid + i * 256;
        int row = id >> 3, cc = id & 7;
        uint32_t off = row * 128 + ((cc * 16) ^ ((row & 7) << 4));
        cp16(sdst + off, g + (size_t)row * K + cc * 8);
    }
}

__global__ __launch_bounds__(256, 1) void gemm_mma(
    const __nv_bfloat16* __restrict__ Ah, const __nv_bfloat16* __restrict__ Al,
    const __nv_bfloat16* __restrict__ Bh, const __nv_bfloat16* __restrict__ Bl,
    float* __restrict__ C, int N, int K)
{
    extern __shared__ char smem[];
    const int tid  = threadIdx.x;
    const int wid  = tid >> 5;
    const int lane = tid & 31;
    const int m0 = blockIdx.y * 128;
    const int n0 = blockIdx.x * 128;
    const int m0w = (wid >> 2) * 64;
    const int n0w = (wid & 3) * 32;

    const uint32_t dyn = smem_u32(smem);
    const uint32_t tbase = (dyn + 1023) & ~1023u;

    const __nv_bfloat16* gAh = Ah + (size_t)m0 * K;
    const __nv_bfloat16* gAl = Al + (size_t)m0 * K;
    const __nv_bfloat16* gBh = Bh + (size_t)n0 * K;
    const __nv_bfloat16* gBl = Bl + (size_t)n0 * K;

    float acc[4][4][4];
#pragma unroll
    for (int i = 0; i < 4; i++)
#pragma unroll
        for (int j = 0; j < 4; j++)
#pragma unroll
            for (int k = 0; k < 4; k++) acc[i][j][k] = 0.f;

    const int lrowA = lane & 15;
    const uint32_t aRow = (uint32_t)(m0w + lrowA) * 128;
    const uint32_t xA = (uint32_t)(lrowA & 7) << 4;
    const uint32_t akh = ((uint32_t)lane >> 4) * 16;
    const int nrow = n0w + (lane & 7) + ((lane >> 4) & 1) * 8;
    const uint32_t bRow = (uint32_t)nrow * 128;
    const uint32_t xB = (uint32_t)(lane & 7) << 4;
    const uint32_t bkh = (((uint32_t)lane >> 3) & 1) * 16;

    issue_tile_loads(gAh, tbase + STG_AH, K, tid);
    issue_tile_loads(gAl, tbase + STG_AL, K, tid);
    issue_tile_loads(gBh, tbase + STG_BH, K, tid);
    issue_tile_loads(gBl, tbase + STG_BL, K, tid);
    CP_COMMIT();

    const int nchunk = K >> 6;
    for (int c = 0; c < nchunk; c++) {
        CP_WAIT0();
        __syncthreads();
        if (c + 1 < nchunk) {
            const uint32_t st = tbase + ((c + 1) & 1) * STG_STRIDE;
            const int k0 = (c + 1) << 6;
            issue_tile_loads(gAh + k0, st + STG_AH, K, tid);
            issue_tile_loads(gAl + k0, st + STG_AL, K, tid);
            issue_tile_loads(gBh + k0, st + STG_BH, K, tid);
            issue_tile_loads(gBl + k0, st + STG_BL, K, tid);
            CP_COMMIT();
        }
        const uint32_t sc = tbase + (c & 1) * STG_STRIDE;
        const uint32_t sAh = sc + STG_AH, sAl = sc + STG_AL;
        const uint32_t sBh = sc + STG_BH, sBl = sc + STG_BL;

#pragma unroll
        for (int ks = 0; ks < 4; ks++) {
            const uint32_t akt = ((uint32_t)ks * 32 + akh) ^ xA;
            const uint32_t bkt = ((uint32_t)ks * 32 + bkh) ^ xB;
            uint32_t ah[4][4], al[4][4], bh[2][4], bl[2][4];
#pragma unroll
            for (int mt = 0; mt < 4; mt++) {
                uint32_t ao = aRow + mt * 2048 + akt;
                LDSM4(ah[mt], sAh + ao);
                LDSM4(al[mt], sAl + ao);
            }
#pragma unroll
            for (int pr = 0; pr < 2; pr++) {
                uint32_t bo = bRow + pr * 2048 + bkt;
                LDSM4(bh[pr], sBh + bo);
                LDSM4(bl[pr], sBl + bo);
            }
#pragma unroll
            for (int mt = 0; mt < 4; mt++) {
#pragma unroll
                for (int nt = 0; nt < 4; nt++) {
                    const int pr = nt >> 1, hf = (nt & 1) * 2;
                    MMA_BF16(acc[mt][nt], ah[mt], bh[pr][hf], bh[pr][hf + 1]);
                    MMA_BF16(acc[mt][nt], ah[mt], bl[pr][hf], bl[pr][hf + 1]);
                    MMA_BF16(acc[mt][nt], al[mt], bh[pr][hf], bh[pr][hf + 1]);
                }
            }
        }
        __syncthreads();
    }

    const int rr = lane >> 2, rc = (lane & 3) * 2;
#pragma unroll
    for (int mt = 0; mt < 4; mt++) {
        const int row = m0 + m0w + mt * 16 + rr;
#pragma unroll
        for (int nt = 0; nt < 4; nt++) {
            const int col = n0 + n0w + nt * 8 + rc;
            *(float2*)&C[(size_t)row * N + col] = make_float2(acc[mt][nt][0], acc[mt][nt][1]);
            *(float2*)&C[(size_t)(row + 8) * N + col] = make_float2(acc[mt][nt][2], acc[mt][nt][3]);
        }
    }
}

// ---------------------------------------------------------------------------
// RoPE + convert (fp32 math — reference computes freqs in fp32 too)
// grid (T/4, NH+2*NKV), block (64,4)
// ---------------------------------------------------------------------------
__global__ void rope_convert(const float* __restrict__ qkv,
                             const int* __restrict__ pos,
                             __half* __restrict__ qb,
                             __half* __restrict__ kb,
                             __half* __restrict__ vb)
{
    const int t = blockIdx.x * 4 + threadIdx.y;
    const int head = blockIdx.y;              // 0..23
    const int i = threadIdx.x;                // 0..63

    if (head < NH + NKV) {
        const float* p = qkv + (size_t)t * QKVN + head * HD_;
        // inv_freq = 1e6^(-2i/128) = 2^(-i * log2(1e6)/64)
        float invf = exp2f((float)i * -0.31143075889569023f);
        float fr = (float)pos[t] * invf;
        float s, c;
        sincosf(fr, &s, &c);
        float x1 = p[i];
        float x2 = p[i + HD_ / 2];
        float y1 = x1 * c - x2 * s;
        float y2 = x2 * c + x1 * s;
        if (head < NH) {
            __half* q = qb + ((size_t)head * TT + t) * HD_;
            q[i] = __float2half_rn(y1);
            q[i + 64] = __float2half_rn(y2);
        } else {
            __half* k = kb + ((size_t)(head - NH) * TT + t) * HD_;
            k[i] = __float2half_rn(y1);
            k[i + 64] = __float2half_rn(y2);
        }
    } else {
        const int kh = head - NH - NKV;
        const float* p = qkv + (size_t)t * QKVN + HID_ + NKV * HD_ + kh * HD_;
        __half* v = vb + ((size_t)kh * TT + t) * HD_;
        v[i] = __float2half_rn(p[i]);
        v[i + 64] = __float2half_rn(p[i + 64]);
    }
}

// ---------------------------------------------------------------------------
// Tensor-core causal GQA flash attention, fp16 operands, fp32 accumulate.
// CTA: 64 queries x 1 head; 4 warps, 128 threads; 3 CTAs/SM.
// Q loaded into stage-1 of the K/V double buffer, fragments extracted once,
// then stage recycled. K-tiles of 64, 2-stage cp.async. Output: bf16 hi/lo.
// 1D grid of 512 CTAs, heavy q-tiles first (LPT greedy).
// ---------------------------------------------------------------------------
#define AKV_STRIDE 32768     // K 16K + V 16K
#define ATTN_SMEM  (2 * AKV_STRIDE + 1024)

__global__ __launch_bounds__(128, 3) void attn_mma(
    const __half* __restrict__ qb, const __half* __restrict__ kb,
    const __half* __restrict__ vbg, const int* __restrict__ pos,
    __nv_bfloat16* __restrict__ oh, __nv_bfloat16* __restrict__ ol)
{
    extern __shared__ char smem[];
    const int bid = blockIdx.x;
    const int h   = bid & (NH - 1);
    const int qt  = (TT / 64 - 1) - (bid >> 4);   // heavy tiles first
    const int q0  = qt * 64;
    const int kvh = h >> 2;
    const int tid = threadIdx.x, wid = tid >> 5, lane = tid & 31;

    const uint32_t dyn = smem_u32(smem);
    const uint32_t KVb = (dyn + 1023) & ~1023u;

    const __half* Qg = qb + ((size_t)h * TT + q0) * HD_;
    const __half* Kg = kb + (size_t)kvh * TT * HD_;
    const __half* Vg = vbg + (size_t)kvh * TT * HD_;

    // Q tile (64 rows x 256B) -> stage 1 (recycled after fragment extraction)
    for (int i = tid; i < 1024; i += 128) {
        int row = i >> 4, cc = i & 15;
        uint32_t off = (uint32_t)row * 256 + (uint32_t)((cc * 16) ^ ((row & 7) << 4));
        cp16(KVb + AKV_STRIDE + off, (const char*)Qg + (size_t)row * 256 + cc * 16);
    }
    // stage 0: K,V tile 0
    for (int i = tid; i < 1024; i += 128) {
        int row = i >> 4, cc = i & 15;
        uint32_t off = (uint32_t)row * 256 + (uint32_t)((cc * 16) ^ ((row & 7) << 4));
        cp16(KVb + off,         (const char*)Kg + (size_t)row * 256 + cc * 16);
        cp16(KVb + 16384 + off, (const char*)Vg + (size_t)row * 256 + cc * 16);
    }
    CP_COMMIT();
    CP_WAIT0();
    __syncthreads();

    // extract loop-invariant Q fragments from stage 1
    uint32_t qfrag[8][4];
    {
        const uint32_t qrow = (uint32_t)(wid * 16 + (lane & 15));
#pragma unroll
        for (int ks = 0; ks < 8; ks++) {
            uint32_t off = qrow * 256 +
                (uint32_t)(((ks * 32) + ((lane >> 4) * 16)) ^ ((qrow & 7) << 4));
            LDSM4(qfrag[ks], KVb + AKV_STRIDE + off);
        }
    }
    __syncthreads();   // all warps done reading Q before stage 1 is overwritten

    const int r0g = q0 + wid * 16 + (lane >> 2);
    const int pq0 = pos[r0g], pq1 = pos[r0g + 8];

    float m0 = -1e30f, m1 = -1e30f, l0 = 0.f, l1 = 0.f;
    float o_acc[16][4];
#pragma unroll
    for (int i = 0; i < 16; i++)
#pragma unroll
        for (int j = 0; j < 4; j++) o_acc[i][j] = 0.f;

    const float CSC = 0.12751661970323393f;   // (1/sqrt(128)) * log2(e)

    const int ntile = qt + 1;
    for (int kt = 0; kt < ntile; kt++) {
        const uint32_t cur = KVb + (uint32_t)(kt & 1) * AKV_STRIDE;
        if (kt + 1 < ntile) {
            const int s0n = (kt + 1) * 64;
            const uint32_t nb = KVb + (uint32_t)((kt + 1) & 1) * AKV_STRIDE;
            for (int i = tid; i < 1024; i += 128) {
                int row = i >> 4, cc = i & 15;
                uint32_t off = (uint32_t)row * 256 + (uint32_t)((cc * 16) ^ ((row & 7) << 4));
                cp16(nb + off,         (const char*)(Kg + (size_t)(s0n + row) * HD_) + cc * 16);
                cp16(nb + 16384 + off, (const char*)(Vg + (size_t)(s0n + row) * HD_) + cc * 16);
            }
            CP_COMMIT();
        }

        // ---- S = Q K^T (warp: 16 rows x 64 keys) ----
        float sa[8][4];
#pragma unroll
        for (int i = 0; i < 8; i++)
#pragma unroll
            for (int j = 0; j < 4; j++) sa[i][j] = 0.f;
        const uint32_t krow = (uint32_t)((lane & 7) + ((lane >> 4) & 1) * 8);
        const uint32_t kch  = (uint32_t)(((lane >> 3) & 1) * 16);
#pragma unroll
        for (int ks = 0; ks < 8; ks++) {
            uint32_t kf[4][4];
#pragma unroll
            for (int ng = 0; ng < 4; ng++) {
                uint32_t row = ng * 16 + krow;
                uint32_t off = row * 256 + (uint32_t)((ks * 32 + kch) ^ ((row & 7) << 4));
                LDSM4(kf[ng], cur + off);
            }
#pragma unroll
            for (int ng = 0; ng < 4; ng++) {
                MMA_F16(sa[2 * ng],     qfrag[ks], kf[ng][0], kf[ng][1]);
                MMA_F16(sa[2 * ng + 1], qfrag[ks], kf[ng][2], kf[ng][3]);
            }
        }

        // ---- scale (+mask on diagonal tile) into log2 domain ----
        const int s0 = kt * 64;
        float e[8][4];
        if (kt == ntile - 1) {
#pragma unroll
            for (int nt = 0; nt < 8; nt++) {
                int c0 = s0 + nt * 8 + (lane & 3) * 2;
                int pk0 = pos[c0], pk1 = pos[c0 + 1];
                e[nt][0] = (pk0 > pq0) ? -1e30f : sa[nt][0] * CSC;
                e[nt][1] = (pk1 > pq0) ? -1e30f : sa[nt][1] * CSC;
                e[nt][2] = (pk0 > pq1) ? -1e30f : sa[nt][2] * CSC;
                e[nt][3] = (pk1 > pq1) ? -1e30f : sa[nt][3] * CSC;
            }
        } else {
#pragma unroll
            for (int nt = 0; nt < 8; nt++)
#pragma unroll
                for (int j = 0; j < 4; j++) e[nt][j] = sa[nt][j] * CSC;
        }

        // ---- online softmax (warp-local, quad shuffles) ----
        float mx0 = -1e30f, mx1 = -1e30f;
#pragma unroll
        for (int nt = 0; nt < 8; nt++) {
            mx0 = fmaxf(mx0, fmaxf(e[nt][0], e[nt][1]));
            mx1 = fmaxf(mx1, fmaxf(e[nt][2], e[nt][3]));
        }
        mx0 = fmaxf(mx0, __shfl_xor_sync(0xffffffffu, mx0, 1));
        mx0 = fmaxf(mx0, __shfl_xor_sync(0xffffffffu, mx0, 2));
        mx1 = fmaxf(mx1, __shfl_xor_sync(0xffffffffu, mx1, 1));
        mx1 = fmaxf(mx1, __shfl_xor_sync(0xffffffffu, mx1, 2));
        const float nm0 = fmaxf(m0, mx0), nm1 = fmaxf(m1, mx1);
        const float al0 = ex2(m0 - nm0), al1 = ex2(m1 - nm1);
        m0 = nm0; m1 = nm1;

        uint32_t pf[4][4];
        float sum0 = 0.f, sum1 = 0.f;
#pragma unroll
        for (int j = 0; j < 4; j++) {
            float pa0 = ex2(e[2 * j][0] - m0),     pa1 = ex2(e[2 * j][1] - m0);
            float pa2 = ex2(e[2 * j][2] - m1),     pa3 = ex2(e[2 * j][3] - m1);
            float pb0 = ex2(e[2 * j + 1][0] - m0), pb1 = ex2(e[2 * j + 1][1] - m0);
            float pb2 = ex2(e[2 * j + 1][2] - m1), pb3 = ex2(e[2 * j + 1][3] - m1);
            sum0 += pa0 + pa1 + pb0 + pb1;
            sum1 += pa2 + pa3 + pb2 + pb3;
            pf[j][0] = packh(pa0, pa1);
            pf[j][1] = packh(pa2, pa3);
            pf[j][2] = packh(pb0, pb1);
            pf[j][3] = packh(pb2, pb3);
        }
        sum0 += __shfl_xor_sync(0xffffffffu, sum0, 1);
        sum0 += __shfl_xor_sync(0xffffffffu, sum0, 2);
        sum1 += __shfl_xor_sync(0xffffffffu, sum1, 1);
        sum1 += __shfl_xor_sync(0xffffffffu, sum1, 2);
        l0 = l0 * al0 + sum0;
        l1 = l1 * al1 + sum1;

        // rescale o_acc (skip when whole warp has alpha == 1: max didn't move)
        if (!__all_sync(0xffffffffu, (al0 == 1.f) && (al1 == 1.f))) {
#pragma unroll
            for (int dt = 0; dt < 16; dt++) {
                o_acc[dt][0] *= al0; o_acc[dt][1] *= al0;
                o_acc[dt][2] *= al1; o_acc[dt][3] *= al1;
            }
        }

        // ---- O += P V  (V via ldmatrix.trans) ----
        const uint32_t vch = (uint32_t)((lane >> 4) * 16);
#pragma unroll
        for (int j = 0; j < 4; j++) {
            const uint32_t vrow = (uint32_t)(j * 16 + (lane & 15));
#pragma unroll
            for (int dt = 0; dt < 8; dt++) {
                uint32_t off = vrow * 256 + (uint32_t)((dt * 32 + vch) ^ ((vrow & 7) << 4));
                uint32_t vf[4];
                LDSM4T(vf, cur + 16384 + off);
                MMA_F16(o_acc[2 * dt],     pf[j], vf[0], vf[1]);
                MMA_F16(o_acc[2 * dt + 1], pf[j], vf[2], vf[3]);
            }
        }

        if (kt + 1 < ntile) {
            CP_WAIT0();        // next tile's K/V ready
            __syncthreads();   // and all warps done with cur before it's recycled
        }
    }

    // ---- epilogue: normalize, split hi/lo, store ----
    const float inv0 = 1.f / l0, inv1 = 1.f / l1;
    const int row0 = q0 + wid * 16 + (lane >> 2);
#pragma unroll
    for (int nt = 0; nt < 16; nt++) {
        const int col = h * HD_ + nt * 8 + (lane & 3) * 2;
        float v0 = o_acc[nt][0] * inv0, v1 = o_acc[nt][1] * inv0;
        float v2 = o_acc[nt][2] * inv1, v3 = o_acc[nt][3] * inv1;
        uint32_t hw0, lw0, hw1, lw1;
        split_pack(v0, v1, hw0, lw0);
        split_pack(v2, v3, hw1, lw1);
        size_t i0 = (size_t)row0 * HID_ + col;
        size_t i1 = (size_t)(row0 + 8) * HID_ + col;
        *(uint32_t*)&oh[i0] = hw0;
        *(uint32_t*)&oh[i1] = hw1;
        *(uint32_t*)&ol[i0] = lw0;
        *(uint32_t*)&ol[i1] = lw1;
    }
}

// ---------------------------------------------------------------------------
extern "C" void kernel_launch(void* const* d_in, const int* in_sizes, int n_in,
                              void* d_out, int out_size)
{
    const float* hidden = (const float*)d_in[0];   // [T, HID]
    const float* w_qkv  = (const float*)d_in[1];   // [HID, 3072]
    const float* w_o    = (const float*)d_in[2];   // [HID, HID]
    const int*   posp   = (const int*)d_in[3];     // [T]
    float* out = (float*)d_out;                    // [T, HID]

    float* qkvp;  cudaGetSymbolAddress((void**)&qkvp, g_qkv);
    __nv_bfloat16 *hh, *hl, *wqh, *wql, *woh, *wol, *ah, *al;
    __half *qbp, *kbp, *vbp;
    cudaGetSymbolAddress((void**)&hh, g_hh);
    cudaGetSymbolAddress((void**)&hl, g_hl);
    cudaGetSymbolAddress((void**)&wqh, g_wqh);
    cudaGetSymbolAddress((void**)&wql, g_wql);
    cudaGetSymbolAddress((void**)&woh, g_woh);
    cudaGetSymbolAddress((void**)&wol, g_wol);
    cudaGetSymbolAddress((void**)&ah, g_ah);
    cudaGetSymbolAddress((void**)&al, g_al);
    cudaGetSymbolAddress((void**)&qbp, g_qb);
    cudaGetSymbolAddress((void**)&kbp, g_kb);
    cudaGetSymbolAddress((void**)&vbp, g_vb);

    cudaFuncSetAttribute((const void*)gemm_mma,
                         cudaFuncAttributeMaxDynamicSharedMemorySize, GEMM_SMEM);
    cudaFuncSetAttribute((const void*)attn_mma,
                         cudaFuncAttributeMaxDynamicSharedMemorySize, ATTN_SMEM);

    // 0) convert operands to bf16 hi/lo
    split_bf16<<<TT * HID_ / 1024, 256>>>(hidden, hh, hl);
    transpose_split<<<dim3(QKVN / 32, HID_ / 32), dim3(32, 8)>>>(w_qkv, wqh, wql, HID_, QKVN);
    transpose_split<<<dim3(HID_ / 32, HID_ / 32), dim3(32, 8)>>>(w_o, woh, wol, HID_, HID_);

    // 1) qkv = hidden @ w_qkv (mma.sync, 3x-bf16)
    gemm_mma<<<dim3(QKVN / 128, TT / 128), 256, GEMM_SMEM>>>(hh, hl, wqh, wql, qkvp, QKVN, HID_);

    // 2) RoPE + fp16 convert (head-major)
    rope_convert<<<dim3(TT / 4, NH + 2 * NKV), dim3(64, 4)>>>(qkvp, posp, qbp, kbp, vbp);

    // 3) tensor-core flash attention, fp16, 64q CTAs, 3/SM (writes bf16 hi/lo)
    attn_mma<<<dim3((TT / 64) * NH), 128, ATTN_SMEM>>>(qbp, kbp, vbp, posp, ah, al);

    // 4) out = attn @ w_o (mma.sync, 3x-bf16)
    gemm_mma<<<dim3(HID_ / 128, TT / 128), 256, GEMM_SMEM>>>(ah, al, woh, wol, out, HID_, HID_);
}

// round 17
// speedup vs baseline: 14.7485x; 1.9585x over previous
#include <cuda_runtime.h>
#include <cuda_bf16.h>
#include <cuda_fp16.h>
#include <stdint.h>
#include <math.h>

#define TT   2048
#define HID_ 2048
#define NH   16
#define NKV  4
#define HD_  128
#define QKVN ((NH + 2 * NKV) * HD_)   // 3072
#define GRP  (NH / NKV)               // 4

// ---------------------------------------------------------------------------
// Scratch (allocation-free rule: static device globals)
// ---------------------------------------------------------------------------
__device__ float g_qkv[TT * QKVN];                      // qkv projection (fp32)
__device__ __align__(256) __half g_hx[TT * HID_];       // hidden fp16
__device__ __align__(256) __half g_wq[QKVN * HID_];     // w_qkv^T fp16 [N][K]
__device__ __align__(256) __half g_wo[HID_ * HID_];     // w_o^T fp16 [N][K]
__device__ __align__(256) __half g_ao[TT * HID_];       // attn out fp16
__device__ __align__(256) __half g_qb[NH * TT * HD_];   // rope'd Q fp16 [h][t][d]
__device__ __align__(256) __half g_kb[NKV * TT * HD_];  // rope'd K fp16 [kh][t][d]
__device__ __align__(256) __half g_vb[NKV * TT * HD_];  // V fp16 [kh][t][d]

// ---------------------------------------------------------------------------
// PTX helpers (baseline ISA only: ldmatrix / mma.sync / cp.async)
// ---------------------------------------------------------------------------
__device__ __forceinline__ uint32_t smem_u32(const void* p) {
    uint32_t a;
    asm("{ .reg .u64 t; cvta.to.shared.u64 t, %1; cvt.u32.u64 %0, t; }" : "=r"(a) : "l"(p));
    return a;
}
#define LDSM4(r, addr) \
    asm volatile("ldmatrix.sync.aligned.m8n8.x4.shared.b16 {%0,%1,%2,%3}, [%4];" \
        : "=r"((r)[0]), "=r"((r)[1]), "=r"((r)[2]), "=r"((r)[3]) : "r"(addr))
#define LDSM4T(r, addr) \
    asm volatile("ldmatrix.sync.aligned.m8n8.x4.trans.shared.b16 {%0,%1,%2,%3}, [%4];" \
        : "=r"((r)[0]), "=r"((r)[1]), "=r"((r)[2]), "=r"((r)[3]) : "r"(addr))
#define MMA_F16(d, a, b0, b1) \
    asm volatile("mma.sync.aligned.m16n8k16.row.col.f32.f16.f16.f32 " \
        "{%0,%1,%2,%3},{%4,%5,%6,%7},{%8,%9},{%0,%1,%2,%3};" \
        : "+f"((d)[0]), "+f"((d)[1]), "+f"((d)[2]), "+f"((d)[3]) \
        : "r"((a)[0]), "r"((a)[1]), "r"((a)[2]), "r"((a)[3]), "r"(b0), "r"(b1))
__device__ __forceinline__ void cp16(uint32_t dst, const void* src) {
    asm volatile("cp.async.cg.shared.global [%0], [%1], 16;" :: "r"(dst), "l"(src));
}
#define CP_COMMIT() asm volatile("cp.async.commit_group;" ::: "memory")
#define CP_WAIT0()  asm volatile("cp.async.wait_group 0;" ::: "memory")
__device__ __forceinline__ float ex2(float x) {
    float r;
    asm("ex2.approx.ftz.f32 %0, %1;" : "=f"(r) : "f"(x));
    return r;
}
__device__ __forceinline__ uint32_t packh(float a, float b) {
    __half2 t = __floats2half2_rn(a, b);
    return reinterpret_cast<uint32_t&>(t);
}

// ---------------------------------------------------------------------------
// fp32 -> fp16 convert (hidden_states)
// ---------------------------------------------------------------------------
__global__ void to_half(const float* __restrict__ x, __half* __restrict__ y)
{
    int i = (blockIdx.x * 256 + threadIdx.x) * 4;
    float4 v = *(const float4*)&x[i];
    uint2 hp;
    hp.x = packh(v.x, v.y);
    hp.y = packh(v.z, v.w);
    *(uint2*)&y[i] = hp;
}

// ---------------------------------------------------------------------------
// Weight transpose + convert: W[K][N] fp32 -> Wt[N][K] fp16
// ---------------------------------------------------------------------------
__global__ void transpose_cvt(const float* __restrict__ W,
                              __half* __restrict__ Tn, int K, int N)
{
    __shared__ float sm[32][33];
    const int n0 = blockIdx.x * 32, k0 = blockIdx.y * 32;
    const int tx = threadIdx.x, ty = threadIdx.y;   // 32 x 8
#pragma unroll
    for (int i = 0; i < 4; i++)
        sm[ty + i * 8][tx] = W[(size_t)(k0 + ty + i * 8) * N + n0 + tx];
    __syncthreads();
#pragma unroll
    for (int i = 0; i < 4; i++)
        Tn[(size_t)(n0 + ty + i * 8) * K + k0 + tx] = __float2half_rn(sm[tx][ty + i * 8]);
}

// ---------------------------------------------------------------------------
// mma.sync GEMM: C[M,N] = A[M,K] @ B^T (B stored [N][K] K-major), fp16 in,
// fp32 out. CTA 128x128, BK=64, 2-stage cp.async, 2 CTAs/SM.
// Warp tile 64x32, m16n8k16.
// ---------------------------------------------------------------------------
#define STG_A 0
#define STG_B 16384
#define STG_STRIDE 32768
#define GEMM_SMEM (2 * STG_STRIDE + 1024)

__device__ __forceinline__ void issue_tile_loads(
    const __half* __restrict__ g, uint32_t sdst, int K, int tid)
{
    // 128 rows x 64 fp16 (128B rows), swizzled; 1024 16B chunks / 256 thr
#pragma unroll
    for (int i = 0; i < 4; i++) {
        int id = tid + i * 256;
        int row = id >> 3, cc = id & 7;
        uint32_t off = row * 128 + ((cc * 16) ^ ((row & 7) << 4));
        cp16(sdst + off, g + (size_t)row * K + cc * 8);
    }
}

__global__ __launch_bounds__(256, 2) void gemm_mma(
    const __half* __restrict__ A, const __half* __restrict__ B,
    float* __restrict__ C, int N, int K)
{
    extern __shared__ char smem[];
    const int tid  = threadIdx.x;
    const int wid  = tid >> 5;
    const int lane = tid & 31;
    const int m0 = blockIdx.y * 128;
    const int n0 = blockIdx.x * 128;
    const int m0w = (wid >> 2) * 64;
    const int n0w = (wid & 3) * 32;

    const uint32_t dyn = smem_u32(smem);
    const uint32_t tbase = (dyn + 1023) & ~1023u;

    const __half* gA = A + (size_t)m0 * K;
    const __half* gB = B + (size_t)n0 * K;

    float acc[4][4][4];
#pragma unroll
    for (int i = 0; i < 4; i++)
#pragma unroll
        for (int j = 0; j < 4; j++)
#pragma unroll
            for (int k = 0; k < 4; k++) acc[i][j][k] = 0.f;

    const int lrowA = lane & 15;
    const uint32_t aRow = (uint32_t)(m0w + lrowA) * 128;
    const uint32_t xA = (uint32_t)(lrowA & 7) << 4;
    const uint32_t akh = ((uint32_t)lane >> 4) * 16;
    const int nrow = n0w + (lane & 7) + ((lane >> 4) & 1) * 8;
    const uint32_t bRow = (uint32_t)nrow * 128;
    const uint32_t xB = (uint32_t)(lane & 7) << 4;
    const uint32_t bkh = (((uint32_t)lane >> 3) & 1) * 16;

    issue_tile_loads(gA, tbase + STG_A, K, tid);
    issue_tile_loads(gB, tbase + STG_B, K, tid);
    CP_COMMIT();

    const int nchunk = K >> 6;
    for (int c = 0; c < nchunk; c++) {
        CP_WAIT0();
        __syncthreads();
        if (c + 1 < nchunk) {
            const uint32_t st = tbase + ((c + 1) & 1) * STG_STRIDE;
            const int k0 = (c + 1) << 6;
            issue_tile_loads(gA + k0, st + STG_A, K, tid);
            issue_tile_loads(gB + k0, st + STG_B, K, tid);
            CP_COMMIT();
        }
        const uint32_t sc = tbase + (c & 1) * STG_STRIDE;
        const uint32_t sA = sc + STG_A, sB = sc + STG_B;

#pragma unroll
        for (int ks = 0; ks < 4; ks++) {
            const uint32_t akt = ((uint32_t)ks * 32 + akh) ^ xA;
            const uint32_t bkt = ((uint32_t)ks * 32 + bkh) ^ xB;
            uint32_t ah[4][4], bh[2][4];
#pragma unroll
            for (int mt = 0; mt < 4; mt++)
                LDSM4(ah[mt], sA + aRow + mt * 2048 + akt);
#pragma unroll
            for (int pr = 0; pr < 2; pr++)
                LDSM4(bh[pr], sB + bRow + pr * 2048 + bkt);
#pragma unroll
            for (int mt = 0; mt < 4; mt++) {
#pragma unroll
                for (int nt = 0; nt < 4; nt++) {
                    const int pr = nt >> 1, hf = (nt & 1) * 2;
                    MMA_F16(acc[mt][nt], ah[mt], bh[pr][hf], bh[pr][hf + 1]);
                }
            }
        }
        __syncthreads();
    }

    const int rr = lane >> 2, rc = (lane & 3) * 2;
#pragma unroll
    for (int mt = 0; mt < 4; mt++) {
        const int row = m0 + m0w + mt * 16 + rr;
#pragma unroll
        for (int nt = 0; nt < 4; nt++) {
            const int col = n0 + n0w + nt * 8 + rc;
            *(float2*)&C[(size_t)row * N + col] = make_float2(acc[mt][nt][0], acc[mt][nt][1]);
            *(float2*)&C[(size_t)(row + 8) * N + col] = make_float2(acc[mt][nt][2], acc[mt][nt][3]);
        }
    }
}

// ---------------------------------------------------------------------------
// RoPE + convert (fp32 math — reference computes freqs in fp32 too)
// grid (T/4, NH+2*NKV), block (64,4)
// ---------------------------------------------------------------------------
__global__ void rope_convert(const float* __restrict__ qkv,
                             const int* __restrict__ pos,
                             __half* __restrict__ qb,
                             __half* __restrict__ kb,
                             __half* __restrict__ vb)
{
    const int t = blockIdx.x * 4 + threadIdx.y;
    const int head = blockIdx.y;              // 0..23
    const int i = threadIdx.x;                // 0..63

    if (head < NH + NKV) {
        const float* p = qkv + (size_t)t * QKVN + head * HD_;
        // inv_freq = 1e6^(-2i/128) = 2^(-i * log2(1e6)/64)
        float invf = exp2f((float)i * -0.31143075889569023f);
        float fr = (float)pos[t] * invf;
        float s, c;
        sincosf(fr, &s, &c);
        float x1 = p[i];
        float x2 = p[i + HD_ / 2];
        float y1 = x1 * c - x2 * s;
        float y2 = x2 * c + x1 * s;
        if (head < NH) {
            __half* q = qb + ((size_t)head * TT + t) * HD_;
            q[i] = __float2half_rn(y1);
            q[i + 64] = __float2half_rn(y2);
        } else {
            __half* k = kb + ((size_t)(head - NH) * TT + t) * HD_;
            k[i] = __float2half_rn(y1);
            k[i + 64] = __float2half_rn(y2);
        }
    } else {
        const int kh = head - NH - NKV;
        const float* p = qkv + (size_t)t * QKVN + HID_ + NKV * HD_ + kh * HD_;
        __half* v = vb + ((size_t)kh * TT + t) * HD_;
        v[i] = __float2half_rn(p[i]);
        v[i + 64] = __float2half_rn(p[i + 64]);
    }
}

// ---------------------------------------------------------------------------
// Tensor-core causal GQA flash attention, fp16 operands, fp32 accumulate.
// CTA: 64 queries x 1 head; 4 warps, 128 threads; 3 CTAs/SM.
// Q loaded into stage-1 of the K/V double buffer, fragments extracted once,
// then stage recycled. K-tiles of 64, 2-stage cp.async. Output: fp16.
// 1D grid of 512 CTAs, heavy q-tiles first (LPT greedy).
// ---------------------------------------------------------------------------
#define AKV_STRIDE 32768     // K 16K + V 16K
#define ATTN_SMEM  (2 * AKV_STRIDE + 1024)

__global__ __launch_bounds__(128, 3) void attn_mma(
    const __half* __restrict__ qb, const __half* __restrict__ kb,
    const __half* __restrict__ vbg, const int* __restrict__ pos,
    __half* __restrict__ ao)
{
    extern __shared__ char smem[];
    const int bid = blockIdx.x;
    const int h   = bid & (NH - 1);
    const int qt  = (TT / 64 - 1) - (bid >> 4);   // heavy tiles first
    const int q0  = qt * 64;
    const int kvh = h >> 2;
    const int tid = threadIdx.x, wid = tid >> 5, lane = tid & 31;

    const uint32_t dyn = smem_u32(smem);
    const uint32_t KVb = (dyn + 1023) & ~1023u;

    const __half* Qg = qb + ((size_t)h * TT + q0) * HD_;
    const __half* Kg = kb + (size_t)kvh * TT * HD_;
    const __half* Vg = vbg + (size_t)kvh * TT * HD_;

    // Q tile (64 rows x 256B) -> stage 1 (recycled after fragment extraction)
    for (int i = tid; i < 1024; i += 128) {
        int row = i >> 4, cc = i & 15;
        uint32_t off = (uint32_t)row * 256 + (uint32_t)((cc * 16) ^ ((row & 7) << 4));
        cp16(KVb + AKV_STRIDE + off, (const char*)Qg + (size_t)row * 256 + cc * 16);
    }
    // stage 0: K,V tile 0
    for (int i = tid; i < 1024; i += 128) {
        int row = i >> 4, cc = i & 15;
        uint32_t off = (uint32_t)row * 256 + (uint32_t)((cc * 16) ^ ((row & 7) << 4));
        cp16(KVb + off,         (const char*)Kg + (size_t)row * 256 + cc * 16);
        cp16(KVb + 16384 + off, (const char*)Vg + (size_t)row * 256 + cc * 16);
    }
    CP_COMMIT();
    CP_WAIT0();
    __syncthreads();

    // extract loop-invariant Q fragments from stage 1
    uint32_t qfrag[8][4];
    {
        const uint32_t qrow = (uint32_t)(wid * 16 + (lane & 15));
#pragma unroll
        for (int ks = 0; ks < 8; ks++) {
            uint32_t off = qrow * 256 +
                (uint32_t)(((ks * 32) + ((lane >> 4) * 16)) ^ ((qrow & 7) << 4));
            LDSM4(qfrag[ks], KVb + AKV_STRIDE + off);
        }
    }
    __syncthreads();   // all warps done reading Q before stage 1 is overwritten

    const int r0g = q0 + wid * 16 + (lane >> 2);
    const int pq0 = pos[r0g], pq1 = pos[r0g + 8];

    float m0 = -1e30f, m1 = -1e30f, l0 = 0.f, l1 = 0.f;
    float o_acc[16][4];
#pragma unroll
    for (int i = 0; i < 16; i++)
#pragma unroll
        for (int j = 0; j < 4; j++) o_acc[i][j] = 0.f;

    const float CSC = 0.12751661970323393f;   // (1/sqrt(128)) * log2(e)

    const int ntile = qt + 1;
    for (int kt = 0; kt < ntile; kt++) {
        const uint32_t cur = KVb + (uint32_t)(kt & 1) * AKV_STRIDE;
        if (kt + 1 < ntile) {
            const int s0n = (kt + 1) * 64;
            const uint32_t nb = KVb + (uint32_t)((kt + 1) & 1) * AKV_STRIDE;
            for (int i = tid; i < 1024; i += 128) {
                int row = i >> 4, cc = i & 15;
                uint32_t off = (uint32_t)row * 256 + (uint32_t)((cc * 16) ^ ((row & 7) << 4));
                cp16(nb + off,         (const char*)(Kg + (size_t)(s0n + row) * HD_) + cc * 16);
                cp16(nb + 16384 + off, (const char*)(Vg + (size_t)(s0n + row) * HD_) + cc * 16);
            }
            CP_COMMIT();
        }

        // ---- S = Q K^T (warp: 16 rows x 64 keys) ----
        float sa[8][4];
#pragma unroll
        for (int i = 0; i < 8; i++)
#pragma unroll
            for (int j = 0; j < 4; j++) sa[i][j] = 0.f;
        const uint32_t krow = (uint32_t)((lane & 7) + ((lane >> 4) & 1) * 8);
        const uint32_t kch  = (uint32_t)(((lane >> 3) & 1) * 16);
#pragma unroll
        for (int ks = 0; ks < 8; ks++) {
            uint32_t kf[4][4];
#pragma unroll
            for (int ng = 0; ng < 4; ng++) {
                uint32_t row = ng * 16 + krow;
                uint32_t off = row * 256 + (uint32_t)((ks * 32 + kch) ^ ((row & 7) << 4));
                LDSM4(kf[ng], cur + off);
            }
#pragma unroll
            for (int ng = 0; ng < 4; ng++) {
                MMA_F16(sa[2 * ng],     qfrag[ks], kf[ng][0], kf[ng][1]);
                MMA_F16(sa[2 * ng + 1], qfrag[ks], kf[ng][2], kf[ng][3]);
            }
        }

        // ---- scale (+mask on diagonal tile) into log2 domain ----
        const int s0 = kt * 64;
        float e[8][4];
        if (kt == ntile - 1) {
#pragma unroll
            for (int nt = 0; nt < 8; nt++) {
                int c0 = s0 + nt * 8 + (lane & 3) * 2;
                int pk0 = pos[c0], pk1 = pos[c0 + 1];
                e[nt][0] = (pk0 > pq0) ? -1e30f : sa[nt][0] * CSC;
                e[nt][1] = (pk1 > pq0) ? -1e30f : sa[nt][1] * CSC;
                e[nt][2] = (pk0 > pq1) ? -1e30f : sa[nt][2] * CSC;
                e[nt][3] = (pk1 > pq1) ? -1e30f : sa[nt][3] * CSC;
            }
        } else {
#pragma unroll
            for (int nt = 0; nt < 8; nt++)
#pragma unroll
                for (int j = 0; j < 4; j++) e[nt][j] = sa[nt][j] * CSC;
        }

        // ---- online softmax (warp-local, quad shuffles) ----
        float mx0 = -1e30f, mx1 = -1e30f;
#pragma unroll
        for (int nt = 0; nt < 8; nt++) {
            mx0 = fmaxf(mx0, fmaxf(e[nt][0], e[nt][1]));
            mx1 = fmaxf(mx1, fmaxf(e[nt][2], e[nt][3]));
        }
        mx0 = fmaxf(mx0, __shfl_xor_sync(0xffffffffu, mx0, 1));
        mx0 = fmaxf(mx0, __shfl_xor_sync(0xffffffffu, mx0, 2));
        mx1 = fmaxf(mx1, __shfl_xor_sync(0xffffffffu, mx1, 1));
        mx1 = fmaxf(mx1, __shfl_xor_sync(0xffffffffu, mx1, 2));
        const float nm0 = fmaxf(m0, mx0), nm1 = fmaxf(m1, mx1);
        const float al0 = ex2(m0 - nm0), al1 = ex2(m1 - nm1);
        m0 = nm0; m1 = nm1;

        uint32_t pf[4][4];
        float sum0 = 0.f, sum1 = 0.f;
#pragma unroll
        for (int j = 0; j < 4; j++) {
            float pa0 = ex2(e[2 * j][0] - m0),     pa1 = ex2(e[2 * j][1] - m0);
            float pa2 = ex2(e[2 * j][2] - m1),     pa3 = ex2(e[2 * j][3] - m1);
            float pb0 = ex2(e[2 * j + 1][0] - m0), pb1 = ex2(e[2 * j + 1][1] - m0);
            float pb2 = ex2(e[2 * j + 1][2] - m1), pb3 = ex2(e[2 * j + 1][3] - m1);
            sum0 += pa0 + pa1 + pb0 + pb1;
            sum1 += pa2 + pa3 + pb2 + pb3;
            pf[j][0] = packh(pa0, pa1);
            pf[j][1] = packh(pa2, pa3);
            pf[j][2] = packh(pb0, pb1);
            pf[j][3] = packh(pb2, pb3);
        }
        sum0 += __shfl_xor_sync(0xffffffffu, sum0, 1);
        sum0 += __shfl_xor_sync(0xffffffffu, sum0, 2);
        sum1 += __shfl_xor_sync(0xffffffffu, sum1, 1);
        sum1 += __shfl_xor_sync(0xffffffffu, sum1, 2);
        l0 = l0 * al0 + sum0;
        l1 = l1 * al1 + sum1;

        // rescale o_acc (skip when whole warp has alpha == 1: max didn't move)
        if (!__all_sync(0xffffffffu, (al0 == 1.f) && (al1 == 1.f))) {
#pragma unroll
            for (int dt = 0; dt < 16; dt++) {
                o_acc[dt][0] *= al0; o_acc[dt][1] *= al0;
                o_acc[dt][2] *= al1; o_acc[dt][3] *= al1;
            }
        }

        // ---- O += P V  (V via ldmatrix.trans) ----
        const uint32_t vch = (uint32_t)((lane >> 4) * 16);
#pragma unroll
        for (int j = 0; j < 4; j++) {
            const uint32_t vrow = (uint32_t)(j * 16 + (lane & 15));
#pragma unroll
            for (int dt = 0; dt < 8; dt++) {
                uint32_t off = vrow * 256 + (uint32_t)((dt * 32 + vch) ^ ((vrow & 7) << 4));
                uint32_t vf[4];
                LDSM4T(vf, cur + 16384 + off);
                MMA_F16(o_acc[2 * dt],     pf[j], vf[0], vf[1]);
                MMA_F16(o_acc[2 * dt + 1], pf[j], vf[2], vf[3]);
            }
        }

        if (kt + 1 < ntile) {
            CP_WAIT0();        // next tile's K/V ready
            __syncthreads();   // and all warps done with cur before it's recycled
        }
    }

    // ---- epilogue: normalize, convert fp16, store ----
    const float inv0 = 1.f / l0, inv1 = 1.f / l1;
    const int row0 = q0 + wid * 16 + (lane >> 2);
#pragma unroll
    for (int nt = 0; nt < 16; nt++) {
        const int col = h * HD_ + nt * 8 + (lane & 3) * 2;
        size_t i0 = (size_t)row0 * HID_ + col;
        size_t i1 = (size_t)(row0 + 8) * HID_ + col;
        *(uint32_t*)&ao[i0] = packh(o_acc[nt][0] * inv0, o_acc[nt][1] * inv0);
        *(uint32_t*)&ao[i1] = packh(o_acc[nt][2] * inv1, o_acc[nt][3] * inv1);
    }
}

// ---------------------------------------------------------------------------
extern "C" void kernel_launch(void* const* d_in, const int* in_sizes, int n_in,
                              void* d_out, int out_size)
{
    const float* hidden = (const float*)d_in[0];   // [T, HID]
    const float* w_qkv  = (const float*)d_in[1];   // [HID, 3072]
    const float* w_o    = (const float*)d_in[2];   // [HID, HID]
    const int*   posp   = (const int*)d_in[3];     // [T]
    float* out = (float*)d_out;                    // [T, HID]

    float* qkvp;  cudaGetSymbolAddress((void**)&qkvp, g_qkv);
    __half *hx, *wq, *wo, *ao, *qbp, *kbp, *vbp;
    cudaGetSymbolAddress((void**)&hx, g_hx);
    cudaGetSymbolAddress((void**)&wq, g_wq);
    cudaGetSymbolAddress((void**)&wo, g_wo);
    cudaGetSymbolAddress((void**)&ao, g_ao);
    cudaGetSymbolAddress((void**)&qbp, g_qb);
    cudaGetSymbolAddress((void**)&kbp, g_kb);
    cudaGetSymbolAddress((void**)&vbp, g_vb);

    cudaFuncSetAttribute((const void*)gemm_mma,
                         cudaFuncAttributeMaxDynamicSharedMemorySize, GEMM_SMEM);
    cudaFuncSetAttribute((const void*)attn_mma,
                         cudaFuncAttributeMaxDynamicSharedMemorySize, ATTN_SMEM);

    // 0) convert operands to fp16
    to_half<<<TT * HID_ / 1024, 256>>>(hidden, hx);
    transpose_cvt<<<dim3(QKVN / 32, HID_ / 32), dim3(32, 8)>>>(w_qkv, wq, HID_, QKVN);
    transpose_cvt<<<dim3(HID_ / 32, HID_ / 32), dim3(32, 8)>>>(w_o, wo, HID_, HID_);

    // 1) qkv = hidden @ w_qkv (mma.sync fp16)
    gemm_mma<<<dim3(QKVN / 128, TT / 128), 256, GEMM_SMEM>>>(hx, wq, qkvp, QKVN, HID_);

    // 2) RoPE + fp16 convert (head-major)
    rope_convert<<<dim3(TT / 4, NH + 2 * NKV), dim3(64, 4)>>>(qkvp, posp, qbp, kbp, vbp);

    // 3) tensor-core flash attention, fp16, 64q CTAs, 3/SM (writes fp16)
    attn_mma<<<dim3((TT / 64) * NH), 128, ATTN_SMEM>>>(qbp, kbp, vbp, posp, ao);

    // 4) out = attn @ w_o (mma.sync fp16)
    gemm_mma<<<dim3(HID_ / 128, TT / 128), 256, GEMM_SMEM>>>(ao, wo, out, HID_, HID_);
}